// round 10
// baseline (speedup 1.0000x reference)
#include <cuda_runtime.h>
#include <cuda_bf16.h>
#include <math.h>

// Problem constants
#define B_ 2
#define T_ 2048
#define C_ 1024
#define H_ 8
#define D_ 1024
#define V_ 32000
#define HD_ (H_*D_)
#define FF_ (4*C_)

// Scratch (device globals; no dynamic allocation allowed)
__device__ float g_x  [B_*T_*C_];
__device__ float g_h  [B_*T_*C_];
__device__ float g_q  [B_*H_*T_*D_];
__device__ float g_k  [B_*H_*T_*D_];
__device__ float g_v  [B_*H_*T_*D_];
__device__ float g_att[B_*T_*HD_];
__device__ float g_ffn[B_*T_*FF_];
__device__ float g_wei[(size_t)B_*H_*T_*T_];
// tf32-rounded weight copies
__device__ float g_cWq [H_*C_*D_];
__device__ float g_cWk [H_*C_*D_];
__device__ float g_cWv [H_*C_*D_];
__device__ float g_cWo [HD_*C_];
__device__ float g_cW1 [C_*FF_];
__device__ float g_cW2 [FF_*C_];
__device__ float g_cWlm[C_*V_];

#define F_BIAS    1
#define F_ADDC    2
#define F_RELU    4
#define F_CAUSALK 8
#define F_TF32    16

__device__ __forceinline__ float tf32r(float x) {
    unsigned r;
    asm("cvt.rna.tf32.f32 %0, %1;" : "=r"(r) : "f"(x));
    return __uint_as_float(r);
}

// ---------------------------------------------------------------------------
// Weight pre-rounding (float4)
// ---------------------------------------------------------------------------
__global__ void cvt_tf32_kernel(const float4* __restrict__ in, float4* __restrict__ out, int n4) {
    int i = blockIdx.x * blockDim.x + threadIdx.x;
    if (i < n4) {
        float4 v = in[i];
        v.x = tf32r(v.x); v.y = tf32r(v.y); v.z = tf32r(v.z); v.w = tf32r(v.w);
        out[i] = v;
    }
}

// ---------------------------------------------------------------------------
// Embedding
// ---------------------------------------------------------------------------
__global__ void embed_kernel(const int* __restrict__ idx,
                             const float* __restrict__ tok,
                             const float* __restrict__ pos) {
    int i = blockIdx.x * blockDim.x + threadIdx.x;
    int c  = i % C_;
    int bt = i / C_;
    int t  = bt % T_;
    g_x[i] = tok[(size_t)idx[bt] * C_ + c] + pos[t * C_ + c];
}

// ---------------------------------------------------------------------------
// LayerNorm (C=1024); output tf32-rounded (feeds GEMM operands)
// ---------------------------------------------------------------------------
__global__ void ln_kernel(const float* __restrict__ in, float* __restrict__ out,
                          const float* __restrict__ g, const float* __restrict__ b) {
    int row = blockIdx.x;
    const float* x = in + (size_t)row * C_;
    float* o = out + (size_t)row * C_;
    int tid = threadIdx.x;

    __shared__ float rs[256], rss[256];
    float s = 0.f, ss = 0.f;
    for (int c = tid; c < C_; c += 256) { float v = x[c]; s += v; ss += v * v; }
    rs[tid] = s; rss[tid] = ss;
    __syncthreads();
    for (int off = 128; off > 0; off >>= 1) {
        if (tid < off) { rs[tid] += rs[tid + off]; rss[tid] += rss[tid + off]; }
        __syncthreads();
    }
    float mean = rs[0] * (1.0f / C_);
    float var  = rss[0] * (1.0f / C_) - mean * mean;
    float inv  = rsqrtf(var + 1e-5f);
    for (int c = tid; c < C_; c += 256)
        o[c] = tf32r((x[c] - mean) * inv * g[c] + b[c]);
}

// ---------------------------------------------------------------------------
// Causal softmax; probs tf32-rounded; zero pad up to next 256 boundary
// (att GEMM uses 256-granular causal K limit)
// ---------------------------------------------------------------------------
__global__ void softmax_kernel(float* __restrict__ wei) {
    int row = blockIdx.x;
    int t = row % T_;
    float* w = wei + (size_t)row * T_;
    int n = t + 1;
    int tid = threadIdx.x;
    __shared__ float red[256];

    float m = -1e30f;
    for (int s = tid; s < n; s += 256) m = fmaxf(m, w[s]);
    red[tid] = m;
    __syncthreads();
    for (int off = 128; off > 0; off >>= 1) {
        if (tid < off) red[tid] = fmaxf(red[tid], red[tid + off]);
        __syncthreads();
    }
    m = red[0];
    __syncthreads();

    float sum = 0.f;
    for (int s = tid; s < n; s += 256) { float e = expf(w[s] - m); w[s] = e; sum += e; }
    red[tid] = sum;
    __syncthreads();
    for (int off = 128; off > 0; off >>= 1) {
        if (tid < off) red[tid] += red[tid + off];
        __syncthreads();
    }
    float inv = 1.f / red[0];
    for (int s = tid; s < n; s += 256) w[s] = tf32r(w[s] * inv);

    int nend = (n + 255) & ~255;
    for (int s = n + tid; s < nend; s += 256) w[s] = 0.f;
}

// ---------------------------------------------------------------------------
// mma helpers (operands pre-rounded to tf32 — no cvt in loop)
// ---------------------------------------------------------------------------
__device__ __forceinline__ void mma8(float* d, const unsigned* a, unsigned b0, unsigned b1) {
    asm volatile(
        "mma.sync.aligned.m16n8k8.row.col.f32.tf32.tf32.f32 "
        "{%0,%1,%2,%3}, {%4,%5,%6,%7}, {%8,%9}, {%0,%1,%2,%3};\n"
        : "+f"(d[0]), "+f"(d[1]), "+f"(d[2]), "+f"(d[3])
        : "r"(a[0]), "r"(a[1]), "r"(a[2]), "r"(a[3]), "r"(b0), "r"(b1));
}

__device__ __forceinline__ void cp16(void* s, const void* g) {
    unsigned sa = (unsigned)__cvta_generic_to_shared(s);
    asm volatile("cp.async.cg.shared.global [%0], [%1], 16;\n" :: "r"(sa), "l"(g));
}
__device__ __forceinline__ void cp_commit() {
    asm volatile("cp.async.commit_group;\n" ::);
}
__device__ __forceinline__ unsigned ldu(const float* p) {
    return __float_as_uint(*p);
}

// A-style tile: [256 rows][k, stride 20]  (banks 20g+tig -> conflict-free)
// B-style tile: [16 k-rows][col, stride 136] (banks 8tig+g -> conflict-free)
#define AP 20
#define BP 136
#define A_W (256*AP)       // floats per A stage (5120)
#define B_W (16*BP)        // floats per B stage (2176)
#define BT_W (128*AP)      // floats per NT B stage (2560)
#define STG_NN (A_W + B_W)  // 7296 floats = 29184 B
#define STG_NT (A_W + BT_W) // 7680 floats = 30720 B
#define SMEM_NN (3*STG_NN*4)
#define SMEM_NT (3*STG_NT*4)

// Warp tile 64x64: 4 m-subtiles x 8 n-subtiles
__device__ __forceinline__ void compute_k8_nn(
    const float (* __restrict__ As)[AP], const float (* __restrict__ Bs)[BP],
    float acc[4][8][4], int kk, int wm, int wn, int g, int tig)
{
    unsigned a[4][4];
#pragma unroll
    for (int mt = 0; mt < 4; mt++) {
        int mrow = wm * 64 + mt * 16;
        a[mt][0] = ldu(&As[mrow + g    ][kk + tig    ]);
        a[mt][1] = ldu(&As[mrow + g + 8][kk + tig    ]);
        a[mt][2] = ldu(&As[mrow + g    ][kk + tig + 4]);
        a[mt][3] = ldu(&As[mrow + g + 8][kk + tig + 4]);
    }
#pragma unroll
    for (int nt = 0; nt < 8; nt++) {
        int ncol = wn * 64 + nt * 8 + g;
        unsigned b0 = ldu(&Bs[kk + tig    ][ncol]);
        unsigned b1 = ldu(&Bs[kk + tig + 4][ncol]);
#pragma unroll
        for (int mt = 0; mt < 4; mt++) mma8(acc[mt][nt], a[mt], b0, b1);
    }
}

__device__ __forceinline__ void compute_k8_nt(
    const float (* __restrict__ As)[AP], const float (* __restrict__ Bt)[AP],
    float acc[4][8][4], int kk, int wm, int wn, int g, int tig)
{
    unsigned a[4][4];
#pragma unroll
    for (int mt = 0; mt < 4; mt++) {
        int mrow = wm * 64 + mt * 16;
        a[mt][0] = ldu(&As[mrow + g    ][kk + tig    ]);
        a[mt][1] = ldu(&As[mrow + g + 8][kk + tig    ]);
        a[mt][2] = ldu(&As[mrow + g    ][kk + tig + 4]);
        a[mt][3] = ldu(&As[mrow + g + 8][kk + tig + 4]);
    }
#pragma unroll
    for (int nt = 0; nt < 8; nt++) {
        int ncol = wn * 64 + nt * 8 + g;
        unsigned b0 = ldu(&Bt[ncol][kk + tig    ]);
        unsigned b1 = ldu(&Bt[ncol][kk + tig + 4]);
#pragma unroll
        for (int mt = 0; mt < 4; mt++) mma8(acc[mt][nt], a[mt], b0, b1);
    }
}

// ---------------------------------------------------------------------------
// tf32 GEMM NN: 256x128 tile, BK=16, 256 threads (8 warps of 64x64, 4m x 2n),
// 3-stage ring, 1 sync/iter
// ---------------------------------------------------------------------------
__global__ void __launch_bounds__(256, 1)
mma_nn(const float* __restrict__ A, const float* __restrict__ Bm,
       float* __restrict__ Cm,
       int K, int lda, int ldb, int ldc,
       long sAb, long sAh, long sBb, long sBh, long sCb, long sCh, int batchH,
       const float* __restrict__ bias, float scale, int flags)
{
    extern __shared__ float dsm[];

    int z  = blockIdx.z;
    int zb = z / batchH, zh = z % batchH;
    A  += zb * sAb + zh * sAh;
    Bm += zb * sBb + zh * sBh;
    Cm += zb * sCb + zh * sCh;

    int bx = blockIdx.x, by = blockIdx.y;
    int row0 = by * 256, col0 = bx * 128;

    int Keff = K;
    if (flags & F_CAUSALK) { int kl = (by + 1) * 256; if (kl < Keff) Keff = kl; }

    int tid  = threadIdx.x;
    int lane = tid & 31, warp = tid >> 5;
    int wm = warp >> 1, wn = warp & 1;       // 4m x 2n warp grid
    int g  = lane >> 2, tig = lane & 3;

    const float* Ag = A  + (size_t)row0 * lda;
    const float* Bg = Bm + col0;
    int arow = tid >> 2, ac = (tid & 3) * 4;   // A: 64 rows x 16k per pass, 4 passes
    int brow = tid >> 5, bc = (tid & 31) * 4;  // B: 8 k-rows x 128 cols per pass, 2 passes

    float acc[4][8][4];
#pragma unroll
    for (int i = 0; i < 4; i++)
#pragma unroll
        for (int j = 0; j < 8; j++)
#pragma unroll
            for (int r = 0; r < 4; r++) acc[i][j][r] = 0.f;

    int iters = Keff / 16;

    // prologue: stages 0 and 1
#pragma unroll
    for (int st = 0; st < 2; st++) {
        if (st < iters) {
            float* As = dsm + st * STG_NN;
            float* Bs = As + A_W;
            int k0 = st * 16;
#pragma unroll
            for (int p = 0; p < 4; p++)
                cp16(&As[(arow + 64 * p) * AP + ac], Ag + (size_t)(arow + 64 * p) * lda + k0 + ac);
#pragma unroll
            for (int p = 0; p < 2; p++)
                cp16(&Bs[(brow + 8 * p) * BP + bc], Bg + (size_t)(k0 + brow + 8 * p) * ldb + bc);
            cp_commit();
        }
    }

    for (int it = 0; it < iters; ++it) {
        if (it + 1 < iters) asm volatile("cp.async.wait_group 1;\n" ::);
        else                asm volatile("cp.async.wait_group 0;\n" ::);
        __syncthreads();
        if (it + 2 < iters) {
            int st = (it + 2) % 3;
            int k0 = (it + 2) * 16;
            float* As = dsm + st * STG_NN;
            float* Bs = As + A_W;
#pragma unroll
            for (int p = 0; p < 4; p++)
                cp16(&As[(arow + 64 * p) * AP + ac], Ag + (size_t)(arow + 64 * p) * lda + k0 + ac);
#pragma unroll
            for (int p = 0; p < 2; p++)
                cp16(&Bs[(brow + 8 * p) * BP + bc], Bg + (size_t)(k0 + brow + 8 * p) * ldb + bc);
            cp_commit();
        }
        const float (*As)[AP] = (const float (*)[AP])(dsm + (it % 3) * STG_NN);
        const float (*Bs)[BP] = (const float (*)[BP])(dsm + (it % 3) * STG_NN + A_W);
        compute_k8_nn(As, Bs, acc, 0, wm, wn, g, tig);
        compute_k8_nn(As, Bs, acc, 8, wm, wn, g, tig);
    }

    // epilogue
#pragma unroll
    for (int mt = 0; mt < 4; mt++) {
#pragma unroll
        for (int nt = 0; nt < 8; nt++) {
            int r = row0 + wm * 64 + mt * 16 + g;
            int c = col0 + wn * 64 + nt * 8 + tig * 2;
#pragma unroll
            for (int half = 0; half < 2; half++) {
                float* p = Cm + (size_t)(r + 8 * half) * ldc + c;
                float x0 = acc[mt][nt][2*half + 0] * scale;
                float x1 = acc[mt][nt][2*half + 1] * scale;
                if (flags & F_BIAS) { x0 += bias[c]; x1 += bias[c + 1]; }
                if (flags & F_RELU) { x0 = fmaxf(x0, 0.f); x1 = fmaxf(x1, 0.f); }
                if (flags & F_TF32) { x0 = tf32r(x0); x1 = tf32r(x1); }
                if (flags & F_ADDC) { x0 += p[0]; x1 += p[1]; }
                p[0] = x0; p[1] = x1;
            }
        }
    }
}

// ---------------------------------------------------------------------------
// tf32 GEMM NT (scores): 256x128 tile; C = scale * A[M,K] @ B[N,K]^T,
// causal tile skip (skip when col tile entirely above diagonal)
// ---------------------------------------------------------------------------
__global__ void __launch_bounds__(256, 1)
mma_nt_scores(const float* __restrict__ A, const float* __restrict__ Bm,
              float* __restrict__ Cm,
              int K, int lda, int ldb, int ldc,
              long sA, long sB, long sC, float scale)
{
    int bx = blockIdx.x, by = blockIdx.y;
    if (bx > 2 * by + 1) return;   // col0 > row0+255 -> fully above diagonal

    extern __shared__ float dsm[];

    int z = blockIdx.z;
    A  += (long)z * sA;
    Bm += (long)z * sB;
    Cm += (long)z * sC;

    int row0 = by * 256, col0 = bx * 128;

    int tid  = threadIdx.x;
    int lane = tid & 31, warp = tid >> 5;
    int wm = warp >> 1, wn = warp & 1;
    int g  = lane >> 2, tig = lane & 3;

    const float* Ag = A  + (size_t)row0 * lda;
    const float* Bg = Bm + (size_t)col0 * ldb;
    int arow = tid >> 2, ac = (tid & 3) * 4;   // A: 64 rows/pass, 4 passes; B: 2 passes

    float acc[4][8][4];
#pragma unroll
    for (int i = 0; i < 4; i++)
#pragma unroll
        for (int j = 0; j < 8; j++)
#pragma unroll
            for (int r = 0; r < 4; r++) acc[i][j][r] = 0.f;

    int iters = K / 16;

    // prologue: stages 0 and 1
#pragma unroll
    for (int st = 0; st < 2; st++) {
        if (st < iters) {
            float* As = dsm + st * STG_NT;
            float* Bt = As + A_W;
            int k0 = st * 16;
#pragma unroll
            for (int p = 0; p < 4; p++)
                cp16(&As[(arow + 64 * p) * AP + ac], Ag + (size_t)(arow + 64 * p) * lda + k0 + ac);
#pragma unroll
            for (int p = 0; p < 2; p++)
                cp16(&Bt[(arow + 64 * p) * AP + ac], Bg + (size_t)(arow + 64 * p) * ldb + k0 + ac);
            cp_commit();
        }
    }

    for (int it = 0; it < iters; ++it) {
        if (it + 1 < iters) asm volatile("cp.async.wait_group 1;\n" ::);
        else                asm volatile("cp.async.wait_group 0;\n" ::);
        __syncthreads();
        if (it + 2 < iters) {
            int st = (it + 2) % 3;
            int k0 = (it + 2) * 16;
            float* As = dsm + st * STG_NT;
            float* Bt = As + A_W;
#pragma unroll
            for (int p = 0; p < 4; p++)
                cp16(&As[(arow + 64 * p) * AP + ac], Ag + (size_t)(arow + 64 * p) * lda + k0 + ac);
#pragma unroll
            for (int p = 0; p < 2; p++)
                cp16(&Bt[(arow + 64 * p) * AP + ac], Bg + (size_t)(arow + 64 * p) * ldb + k0 + ac);
            cp_commit();
        }
        const float (*As)[AP] = (const float (*)[AP])(dsm + (it % 3) * STG_NT);
        const float (*Bt)[AP] = (const float (*)[AP])(dsm + (it % 3) * STG_NT + A_W);
        compute_k8_nt(As, Bt, acc, 0, wm, wn, g, tig);
        compute_k8_nt(As, Bt, acc, 8, wm, wn, g, tig);
    }

#pragma unroll
    for (int mt = 0; mt < 4; mt++) {
#pragma unroll
        for (int nt = 0; nt < 8; nt++) {
            int r = row0 + wm * 64 + mt * 16 + g;
            int c = col0 + wn * 64 + nt * 8 + tig * 2;
#pragma unroll
            for (int half = 0; half < 2; half++) {
                float* p = Cm + (size_t)(r + 8 * half) * ldc + c;
                p[0] = acc[mt][nt][2*half + 0] * scale;
                p[1] = acc[mt][nt][2*half + 1] * scale;
            }
        }
    }
}

// ---------------------------------------------------------------------------
// Host launch
// ---------------------------------------------------------------------------
extern "C" void kernel_launch(void* const* d_in, const int* in_sizes, int n_in,
                              void* d_out, int out_size) {
    const int*   idx = (const int*)  d_in[0];
    const float* tok = (const float*)d_in[1];
    const float* pos = (const float*)d_in[2];
    const float* Wq  = (const float*)d_in[3];
    const float* Wk  = (const float*)d_in[4];
    const float* Wv  = (const float*)d_in[5];
    const float* Wo  = (const float*)d_in[6];
    const float* bo  = (const float*)d_in[7];
    const float* W1  = (const float*)d_in[8];
    const float* b1  = (const float*)d_in[9];
    const float* W2  = (const float*)d_in[10];
    const float* b2  = (const float*)d_in[11];
    const float* g1  = (const float*)d_in[12];
    const float* be1 = (const float*)d_in[13];
    const float* g2  = (const float*)d_in[14];
    const float* be2 = (const float*)d_in[15];
    const float* gf  = (const float*)d_in[16];
    const float* bef = (const float*)d_in[17];
    const float* Wlm = (const float*)d_in[18];
    const float* blm = (const float*)d_in[19];
    float* out = (float*)d_out;

    float *x, *h, *q, *k, *v, *att, *ffn, *wei;
    float *cWq, *cWk, *cWv, *cWo, *cW1, *cW2, *cWlm;
    cudaGetSymbolAddress((void**)&x,   g_x);
    cudaGetSymbolAddress((void**)&h,   g_h);
    cudaGetSymbolAddress((void**)&q,   g_q);
    cudaGetSymbolAddress((void**)&k,   g_k);
    cudaGetSymbolAddress((void**)&v,   g_v);
    cudaGetSymbolAddress((void**)&att, g_att);
    cudaGetSymbolAddress((void**)&ffn, g_ffn);
    cudaGetSymbolAddress((void**)&wei, g_wei);
    cudaGetSymbolAddress((void**)&cWq, g_cWq);
    cudaGetSymbolAddress((void**)&cWk, g_cWk);
    cudaGetSymbolAddress((void**)&cWv, g_cWv);
    cudaGetSymbolAddress((void**)&cWo, g_cWo);
    cudaGetSymbolAddress((void**)&cW1, g_cW1);
    cudaGetSymbolAddress((void**)&cW2, g_cW2);
    cudaGetSymbolAddress((void**)&cWlm, g_cWlm);

    cudaFuncSetAttribute(mma_nn,        cudaFuncAttributeMaxDynamicSharedMemorySize, SMEM_NN);
    cudaFuncSetAttribute(mma_nt_scores, cudaFuncAttributeMaxDynamicSharedMemorySize, SMEM_NT);

    // 0. pre-round weights to tf32 format
    {
        auto cvt = [](const float* in, float* outp, long n) {
            int n4 = (int)(n / 4);
            cvt_tf32_kernel<<<(n4 + 255) / 256, 256>>>((const float4*)in, (float4*)outp, n4);
        };
        cvt(Wq, cWq, (long)H_*C_*D_);
        cvt(Wk, cWk, (long)H_*C_*D_);
        cvt(Wv, cWv, (long)H_*C_*D_);
        cvt(Wo, cWo, (long)HD_*C_);
        cvt(W1, cW1, (long)C_*FF_);
        cvt(W2, cW2, (long)FF_*C_);
        cvt(Wlm, cWlm, (long)C_*V_);
    }

    // 1. embedding
    embed_kernel<<<(B_*T_*C_)/256, 256>>>(idx, tok, pos);

    // 2. LN1
    ln_kernel<<<B_*T_, 256>>>(x, h, g1, be1);

    // 3. q,k,v projections
    {
        dim3 grid(D_/128, T_/256, B_*H_);
        long sAb = (long)T_*C_, sBh = (long)C_*D_;
        long sCb = (long)H_*T_*D_, sCh = (long)T_*D_;
        mma_nn<<<grid, 256, SMEM_NN>>>(h, cWq, q, C_, C_, D_, D_,
                              sAb, 0, 0, sBh, sCb, sCh, H_, nullptr, 1.f, F_TF32);
        mma_nn<<<grid, 256, SMEM_NN>>>(h, cWk, k, C_, C_, D_, D_,
                              sAb, 0, 0, sBh, sCb, sCh, H_, nullptr, 1.f, F_TF32);
        mma_nn<<<grid, 256, SMEM_NN>>>(h, cWv, v, C_, C_, D_, D_,
                              sAb, 0, 0, sBh, sCb, sCh, H_, nullptr, 1.f, F_TF32);
    }

    // 4. scores
    {
        dim3 grid(T_/128, T_/256, B_*H_);
        mma_nt_scores<<<grid, 256, SMEM_NT>>>(q, k, wei, D_, D_, D_, T_,
                                     (long)T_*D_, (long)T_*D_, (long)T_*T_,
                                     rsqrtf((float)D_));
    }

    // 5. softmax (zero pad to 256 boundary for coarser causal K)
    softmax_kernel<<<B_*H_*T_, 256>>>(wei);

    // 6. att = wei @ v  ([B,T,H*D] layout, 256-granular causal K-limit)
    {
        dim3 grid(D_/128, T_/256, B_*H_);
        mma_nn<<<grid, 256, SMEM_NN>>>(wei, v, att, T_, T_, D_, HD_,
                              (long)H_*T_*T_, (long)T_*T_,
                              (long)H_*T_*D_, (long)T_*D_,
                              (long)T_*HD_, (long)D_, H_,
                              nullptr, 1.f, F_CAUSALK | F_TF32);
    }

    // 7. x += att @ Wo + bo
    mma_nn<<<dim3(C_/128, (B_*T_)/256, 1), 256, SMEM_NN>>>(
        att, cWo, x, HD_, HD_, C_, C_,
        0, 0, 0, 0, 0, 0, 1, bo, 1.f, F_BIAS | F_ADDC);

    // 8. LN2
    ln_kernel<<<B_*T_, 256>>>(x, h, g2, be2);

    // 9. ffn = relu(h @ W1 + b1)
    mma_nn<<<dim3(FF_/128, (B_*T_)/256, 1), 256, SMEM_NN>>>(
        h, cW1, ffn, C_, C_, FF_, FF_,
        0, 0, 0, 0, 0, 0, 1, b1, 1.f, F_BIAS | F_RELU | F_TF32);

    // 10. x += ffn @ W2 + b2
    mma_nn<<<dim3(C_/128, (B_*T_)/256, 1), 256, SMEM_NN>>>(
        ffn, cW2, x, FF_, FF_, C_, C_,
        0, 0, 0, 0, 0, 0, 1, b2, 1.f, F_BIAS | F_ADDC);

    // 11. final LN
    ln_kernel<<<B_*T_, 256>>>(x, h, gf, bef);

    // 12. logits = h @ Wlm + blm
    mma_nn<<<dim3(V_/128, (B_*T_)/256, 1), 256, SMEM_NN>>>(
        h, cWlm, out, C_, C_, V_, V_,
        0, 0, 0, 0, 0, 0, 1, blm, 1.f, F_BIAS);
}

// round 11
// speedup vs baseline: 1.2382x; 1.2382x over previous
#include <cuda_runtime.h>
#include <cuda_bf16.h>
#include <math.h>

// Problem constants
#define B_ 2
#define T_ 2048
#define C_ 1024
#define H_ 8
#define D_ 1024
#define V_ 32000
#define HD_ (H_*D_)
#define FF_ (4*C_)

// Scratch (device globals; no dynamic allocation allowed)
__device__ float g_x  [B_*T_*C_];
__device__ float g_h  [B_*T_*C_];
__device__ float g_q  [B_*H_*T_*D_];
__device__ float g_k  [B_*H_*T_*D_];
__device__ float g_v  [B_*H_*T_*D_];
__device__ float g_att[B_*T_*HD_];
__device__ float g_ffn[B_*T_*FF_];
__device__ float g_wei[(size_t)B_*H_*T_*T_];
// tf32-rounded weight copies
__device__ float g_cWq [H_*C_*D_];
__device__ float g_cWk [H_*C_*D_];
__device__ float g_cWv [H_*C_*D_];
__device__ float g_cWo [HD_*C_];
__device__ float g_cW1 [C_*FF_];
__device__ float g_cW2 [FF_*C_];
__device__ float g_cWlm[C_*V_];

#define F_BIAS    1
#define F_ADDC    2
#define F_RELU    4
#define F_CAUSALK 8
#define F_TF32    16

__device__ __forceinline__ float tf32r(float x) {
    unsigned r;
    asm("cvt.rna.tf32.f32 %0, %1;" : "=r"(r) : "f"(x));
    return __uint_as_float(r);
}

// ---------------------------------------------------------------------------
// Weight pre-rounding (float4)
// ---------------------------------------------------------------------------
__global__ void cvt_tf32_kernel(const float4* __restrict__ in, float4* __restrict__ out, int n4) {
    int i = blockIdx.x * blockDim.x + threadIdx.x;
    if (i < n4) {
        float4 v = in[i];
        v.x = tf32r(v.x); v.y = tf32r(v.y); v.z = tf32r(v.z); v.w = tf32r(v.w);
        out[i] = v;
    }
}

// ---------------------------------------------------------------------------
// Embedding
// ---------------------------------------------------------------------------
__global__ void embed_kernel(const int* __restrict__ idx,
                             const float* __restrict__ tok,
                             const float* __restrict__ pos) {
    int i = blockIdx.x * blockDim.x + threadIdx.x;
    int c  = i % C_;
    int bt = i / C_;
    int t  = bt % T_;
    g_x[i] = tok[(size_t)idx[bt] * C_ + c] + pos[t * C_ + c];
}

// ---------------------------------------------------------------------------
// LayerNorm (C=1024); output tf32-rounded (feeds GEMM operands)
// ---------------------------------------------------------------------------
__global__ void ln_kernel(const float* __restrict__ in, float* __restrict__ out,
                          const float* __restrict__ g, const float* __restrict__ b) {
    int row = blockIdx.x;
    const float* x = in + (size_t)row * C_;
    float* o = out + (size_t)row * C_;
    int tid = threadIdx.x;

    __shared__ float rs[256], rss[256];
    float s = 0.f, ss = 0.f;
    for (int c = tid; c < C_; c += 256) { float v = x[c]; s += v; ss += v * v; }
    rs[tid] = s; rss[tid] = ss;
    __syncthreads();
    for (int off = 128; off > 0; off >>= 1) {
        if (tid < off) { rs[tid] += rs[tid + off]; rss[tid] += rss[tid + off]; }
        __syncthreads();
    }
    float mean = rs[0] * (1.0f / C_);
    float var  = rss[0] * (1.0f / C_) - mean * mean;
    float inv  = rsqrtf(var + 1e-5f);
    for (int c = tid; c < C_; c += 256)
        o[c] = tf32r((x[c] - mean) * inv * g[c] + b[c]);
}

// ---------------------------------------------------------------------------
// Causal softmax; probs tf32-rounded; zero pad up to next 128 boundary
// ---------------------------------------------------------------------------
__global__ void softmax_kernel(float* __restrict__ wei) {
    int row = blockIdx.x;
    int t = row % T_;
    float* w = wei + (size_t)row * T_;
    int n = t + 1;
    int tid = threadIdx.x;
    __shared__ float red[256];

    float m = -1e30f;
    for (int s = tid; s < n; s += 256) m = fmaxf(m, w[s]);
    red[tid] = m;
    __syncthreads();
    for (int off = 128; off > 0; off >>= 1) {
        if (tid < off) red[tid] = fmaxf(red[tid], red[tid + off]);
        __syncthreads();
    }
    m = red[0];
    __syncthreads();

    float sum = 0.f;
    for (int s = tid; s < n; s += 256) { float e = expf(w[s] - m); w[s] = e; sum += e; }
    red[tid] = sum;
    __syncthreads();
    for (int off = 128; off > 0; off >>= 1) {
        if (tid < off) red[tid] += red[tid + off];
        __syncthreads();
    }
    float inv = 1.f / red[0];
    for (int s = tid; s < n; s += 256) w[s] = tf32r(w[s] * inv);

    int nend = (n + 127) & ~127;
    for (int s = n + tid; s < nend; s += 256) w[s] = 0.f;
}

// ---------------------------------------------------------------------------
// mma helpers (operands pre-rounded to tf32 — no cvt in loop)
// ---------------------------------------------------------------------------
__device__ __forceinline__ void mma8(float* d, const unsigned* a, unsigned b0, unsigned b1) {
    asm volatile(
        "mma.sync.aligned.m16n8k8.row.col.f32.tf32.tf32.f32 "
        "{%0,%1,%2,%3}, {%4,%5,%6,%7}, {%8,%9}, {%0,%1,%2,%3};\n"
        : "+f"(d[0]), "+f"(d[1]), "+f"(d[2]), "+f"(d[3])
        : "r"(a[0]), "r"(a[1]), "r"(a[2]), "r"(a[3]), "r"(b0), "r"(b1));
}

__device__ __forceinline__ void cp16(void* s, const void* g) {
    unsigned sa = (unsigned)__cvta_generic_to_shared(s);
    asm volatile("cp.async.cg.shared.global [%0], [%1], 16;\n" :: "r"(sa), "l"(g));
}
__device__ __forceinline__ void cp_commit() {
    asm volatile("cp.async.commit_group;\n" ::);
}
__device__ __forceinline__ unsigned ldu(const float* p) {
    return __float_as_uint(*p);
}

// A-style tile: [128 rows][k, stride 36]  (36 % 32 == 4 -> frag banks 4g+tig, conflict-free)
// B-style tile: [32 k-rows][col, stride 136] (8tig+g -> conflict-free)
#define AP 36
#define BP 136
#define A_W (128*AP)        // floats per A stage (4608)
#define B_W (32*BP)         // floats per B stage (4352)
#define STG_NN (A_W + B_W)  // 8960 floats = 35840 B
#define STG_NT (A_W + A_W)  // 9216 floats = 36864 B
#define SMEM_NN (3*STG_NN*4)
#define SMEM_NT (3*STG_NT*4)

// Warp tile 64x64: 4 m-subtiles x 8 n-subtiles
__device__ __forceinline__ void compute_k8_nn(
    const float (* __restrict__ As)[AP], const float (* __restrict__ Bs)[BP],
    float acc[4][8][4], int kk, int wm, int wn, int g, int tig)
{
    unsigned a[4][4];
#pragma unroll
    for (int mt = 0; mt < 4; mt++) {
        int mrow = wm * 64 + mt * 16;
        a[mt][0] = ldu(&As[mrow + g    ][kk + tig    ]);
        a[mt][1] = ldu(&As[mrow + g + 8][kk + tig    ]);
        a[mt][2] = ldu(&As[mrow + g    ][kk + tig + 4]);
        a[mt][3] = ldu(&As[mrow + g + 8][kk + tig + 4]);
    }
#pragma unroll
    for (int nt = 0; nt < 8; nt++) {
        int ncol = wn * 64 + nt * 8 + g;
        unsigned b0 = ldu(&Bs[kk + tig    ][ncol]);
        unsigned b1 = ldu(&Bs[kk + tig + 4][ncol]);
#pragma unroll
        for (int mt = 0; mt < 4; mt++) mma8(acc[mt][nt], a[mt], b0, b1);
    }
}

__device__ __forceinline__ void compute_k8_nt(
    const float (* __restrict__ As)[AP], const float (* __restrict__ Bt)[AP],
    float acc[4][8][4], int kk, int wm, int wn, int g, int tig)
{
    unsigned a[4][4];
#pragma unroll
    for (int mt = 0; mt < 4; mt++) {
        int mrow = wm * 64 + mt * 16;
        a[mt][0] = ldu(&As[mrow + g    ][kk + tig    ]);
        a[mt][1] = ldu(&As[mrow + g + 8][kk + tig    ]);
        a[mt][2] = ldu(&As[mrow + g    ][kk + tig + 4]);
        a[mt][3] = ldu(&As[mrow + g + 8][kk + tig + 4]);
    }
#pragma unroll
    for (int nt = 0; nt < 8; nt++) {
        int ncol = wn * 64 + nt * 8 + g;
        unsigned b0 = ldu(&Bt[ncol][kk + tig    ]);
        unsigned b1 = ldu(&Bt[ncol][kk + tig + 4]);
#pragma unroll
        for (int mt = 0; mt < 4; mt++) mma8(acc[mt][nt], a[mt], b0, b1);
    }
}

// ---------------------------------------------------------------------------
// tf32 GEMM NN: 128x128 tile, BK=32, 128 threads, 3-stage ring, 1 sync/iter
// ---------------------------------------------------------------------------
__global__ void __launch_bounds__(128, 2)
mma_nn(const float* __restrict__ A, const float* __restrict__ Bm,
       float* __restrict__ Cm,
       int K, int lda, int ldb, int ldc,
       long sAb, long sAh, long sBb, long sBh, long sCb, long sCh, int batchH,
       const float* __restrict__ bias, float scale, int flags)
{
    extern __shared__ float dsm[];

    int z  = blockIdx.z;
    int zb = z / batchH, zh = z % batchH;
    A  += zb * sAb + zh * sAh;
    Bm += zb * sBb + zh * sBh;
    Cm += zb * sCb + zh * sCh;

    int bx = blockIdx.x, by = blockIdx.y;
    int row0 = by * 128, col0 = bx * 128;

    int Keff = K;
    if (flags & F_CAUSALK) { int kl = (by + 1) * 128; if (kl < Keff) Keff = kl; }

    int tid  = threadIdx.x;
    int lane = tid & 31, warp = tid >> 5;
    int wm = warp >> 1, wn = warp & 1;
    int g  = lane >> 2, tig = lane & 3;

    const float* Ag = A  + (size_t)row0 * lda;
    const float* Bg = Bm + col0;
    int lrow = tid >> 3, lch = (tid & 7) * 4;   // A: 16 rows x 32k per pass, 8 passes
    int brow = tid >> 5, bc = (tid & 31) * 4;   // B: 4 k-rows x 128 cols per pass, 8 passes

    float acc[4][8][4];
#pragma unroll
    for (int i = 0; i < 4; i++)
#pragma unroll
        for (int j = 0; j < 8; j++)
#pragma unroll
            for (int r = 0; r < 4; r++) acc[i][j][r] = 0.f;

    int iters = Keff / 32;

    // prologue: stages 0 and 1
#pragma unroll
    for (int st = 0; st < 2; st++) {
        if (st < iters) {
            float* As = dsm + st * STG_NN;
            float* Bs = As + A_W;
            int k0 = st * 32;
#pragma unroll
            for (int p = 0; p < 8; p++)
                cp16(&As[(lrow + 16 * p) * AP + lch], Ag + (size_t)(lrow + 16 * p) * lda + k0 + lch);
#pragma unroll
            for (int p = 0; p < 8; p++)
                cp16(&Bs[(brow + 4 * p) * BP + bc], Bg + (size_t)(k0 + brow + 4 * p) * ldb + bc);
            cp_commit();
        }
    }

    for (int it = 0; it < iters; ++it) {
        if (it + 1 < iters) asm volatile("cp.async.wait_group 1;\n" ::);
        else                asm volatile("cp.async.wait_group 0;\n" ::);
        __syncthreads();
        if (it + 2 < iters) {
            int st = (it + 2) % 3;
            int k0 = (it + 2) * 32;
            float* As = dsm + st * STG_NN;
            float* Bs = As + A_W;
#pragma unroll
            for (int p = 0; p < 8; p++)
                cp16(&As[(lrow + 16 * p) * AP + lch], Ag + (size_t)(lrow + 16 * p) * lda + k0 + lch);
#pragma unroll
            for (int p = 0; p < 8; p++)
                cp16(&Bs[(brow + 4 * p) * BP + bc], Bg + (size_t)(k0 + brow + 4 * p) * ldb + bc);
            cp_commit();
        }
        const float (*As)[AP] = (const float (*)[AP])(dsm + (it % 3) * STG_NN);
        const float (*Bs)[BP] = (const float (*)[BP])(dsm + (it % 3) * STG_NN + A_W);
        compute_k8_nn(As, Bs, acc, 0,  wm, wn, g, tig);
        compute_k8_nn(As, Bs, acc, 8,  wm, wn, g, tig);
        compute_k8_nn(As, Bs, acc, 16, wm, wn, g, tig);
        compute_k8_nn(As, Bs, acc, 24, wm, wn, g, tig);
    }

    // epilogue
#pragma unroll
    for (int mt = 0; mt < 4; mt++) {
#pragma unroll
        for (int nt = 0; nt < 8; nt++) {
            int r = row0 + wm * 64 + mt * 16 + g;
            int c = col0 + wn * 64 + nt * 8 + tig * 2;
#pragma unroll
            for (int half = 0; half < 2; half++) {
                float* p = Cm + (size_t)(r + 8 * half) * ldc + c;
                float x0 = acc[mt][nt][2*half + 0] * scale;
                float x1 = acc[mt][nt][2*half + 1] * scale;
                if (flags & F_BIAS) { x0 += bias[c]; x1 += bias[c + 1]; }
                if (flags & F_RELU) { x0 = fmaxf(x0, 0.f); x1 = fmaxf(x1, 0.f); }
                if (flags & F_TF32) { x0 = tf32r(x0); x1 = tf32r(x1); }
                if (flags & F_ADDC) { x0 += p[0]; x1 += p[1]; }
                p[0] = x0; p[1] = x1;
            }
        }
    }
}

// ---------------------------------------------------------------------------
// tf32 GEMM NT (scores): 128x128 tile, BK=32; causal tile skip
// ---------------------------------------------------------------------------
__global__ void __launch_bounds__(128, 2)
mma_nt_scores(const float* __restrict__ A, const float* __restrict__ Bm,
              float* __restrict__ Cm,
              int K, int lda, int ldb, int ldc,
              long sA, long sB, long sC, float scale)
{
    int bx = blockIdx.x, by = blockIdx.y;
    if (bx > by) return;

    extern __shared__ float dsm[];

    int z = blockIdx.z;
    A  += (long)z * sA;
    Bm += (long)z * sB;
    Cm += (long)z * sC;

    int row0 = by * 128, col0 = bx * 128;

    int tid  = threadIdx.x;
    int lane = tid & 31, warp = tid >> 5;
    int wm = warp >> 1, wn = warp & 1;
    int g  = lane >> 2, tig = lane & 3;

    const float* Ag = A  + (size_t)row0 * lda;
    const float* Bg = Bm + (size_t)col0 * ldb;
    int lrow = tid >> 3, lch = (tid & 7) * 4;

    float acc[4][8][4];
#pragma unroll
    for (int i = 0; i < 4; i++)
#pragma unroll
        for (int j = 0; j < 8; j++)
#pragma unroll
            for (int r = 0; r < 4; r++) acc[i][j][r] = 0.f;

    int iters = K / 32;

    // prologue: stages 0 and 1
#pragma unroll
    for (int st = 0; st < 2; st++) {
        if (st < iters) {
            float* As = dsm + st * STG_NT;
            float* Bt = As + A_W;
            int k0 = st * 32;
#pragma unroll
            for (int p = 0; p < 8; p++)
                cp16(&As[(lrow + 16 * p) * AP + lch], Ag + (size_t)(lrow + 16 * p) * lda + k0 + lch);
#pragma unroll
            for (int p = 0; p < 8; p++)
                cp16(&Bt[(lrow + 16 * p) * AP + lch], Bg + (size_t)(lrow + 16 * p) * ldb + k0 + lch);
            cp_commit();
        }
    }

    for (int it = 0; it < iters; ++it) {
        if (it + 1 < iters) asm volatile("cp.async.wait_group 1;\n" ::);
        else                asm volatile("cp.async.wait_group 0;\n" ::);
        __syncthreads();
        if (it + 2 < iters) {
            int st = (it + 2) % 3;
            int k0 = (it + 2) * 32;
            float* As = dsm + st * STG_NT;
            float* Bt = As + A_W;
#pragma unroll
            for (int p = 0; p < 8; p++)
                cp16(&As[(lrow + 16 * p) * AP + lch], Ag + (size_t)(lrow + 16 * p) * lda + k0 + lch);
#pragma unroll
            for (int p = 0; p < 8; p++)
                cp16(&Bt[(lrow + 16 * p) * AP + lch], Bg + (size_t)(lrow + 16 * p) * ldb + k0 + lch);
            cp_commit();
        }
        const float (*As)[AP] = (const float (*)[AP])(dsm + (it % 3) * STG_NT);
        const float (*Bt)[AP] = (const float (*)[AP])(dsm + (it % 3) * STG_NT + A_W);
        compute_k8_nt(As, Bt, acc, 0,  wm, wn, g, tig);
        compute_k8_nt(As, Bt, acc, 8,  wm, wn, g, tig);
        compute_k8_nt(As, Bt, acc, 16, wm, wn, g, tig);
        compute_k8_nt(As, Bt, acc, 24, wm, wn, g, tig);
    }

#pragma unroll
    for (int mt = 0; mt < 4; mt++) {
#pragma unroll
        for (int nt = 0; nt < 8; nt++) {
            int r = row0 + wm * 64 + mt * 16 + g;
            int c = col0 + wn * 64 + nt * 8 + tig * 2;
#pragma unroll
            for (int half = 0; half < 2; half++) {
                float* p = Cm + (size_t)(r + 8 * half) * ldc + c;
                p[0] = acc[mt][nt][2*half + 0] * scale;
                p[1] = acc[mt][nt][2*half + 1] * scale;
            }
        }
    }
}

// ---------------------------------------------------------------------------
// Host launch
// ---------------------------------------------------------------------------
extern "C" void kernel_launch(void* const* d_in, const int* in_sizes, int n_in,
                              void* d_out, int out_size) {
    const int*   idx = (const int*)  d_in[0];
    const float* tok = (const float*)d_in[1];
    const float* pos = (const float*)d_in[2];
    const float* Wq  = (const float*)d_in[3];
    const float* Wk  = (const float*)d_in[4];
    const float* Wv  = (const float*)d_in[5];
    const float* Wo  = (const float*)d_in[6];
    const float* bo  = (const float*)d_in[7];
    const float* W1  = (const float*)d_in[8];
    const float* b1  = (const float*)d_in[9];
    const float* W2  = (const float*)d_in[10];
    const float* b2  = (const float*)d_in[11];
    const float* g1  = (const float*)d_in[12];
    const float* be1 = (const float*)d_in[13];
    const float* g2  = (const float*)d_in[14];
    const float* be2 = (const float*)d_in[15];
    const float* gf  = (const float*)d_in[16];
    const float* bef = (const float*)d_in[17];
    const float* Wlm = (const float*)d_in[18];
    const float* blm = (const float*)d_in[19];
    float* out = (float*)d_out;

    float *x, *h, *q, *k, *v, *att, *ffn, *wei;
    float *cWq, *cWk, *cWv, *cWo, *cW1, *cW2, *cWlm;
    cudaGetSymbolAddress((void**)&x,   g_x);
    cudaGetSymbolAddress((void**)&h,   g_h);
    cudaGetSymbolAddress((void**)&q,   g_q);
    cudaGetSymbolAddress((void**)&k,   g_k);
    cudaGetSymbolAddress((void**)&v,   g_v);
    cudaGetSymbolAddress((void**)&att, g_att);
    cudaGetSymbolAddress((void**)&ffn, g_ffn);
    cudaGetSymbolAddress((void**)&wei, g_wei);
    cudaGetSymbolAddress((void**)&cWq, g_cWq);
    cudaGetSymbolAddress((void**)&cWk, g_cWk);
    cudaGetSymbolAddress((void**)&cWv, g_cWv);
    cudaGetSymbolAddress((void**)&cWo, g_cWo);
    cudaGetSymbolAddress((void**)&cW1, g_cW1);
    cudaGetSymbolAddress((void**)&cW2, g_cW2);
    cudaGetSymbolAddress((void**)&cWlm, g_cWlm);

    cudaFuncSetAttribute(mma_nn,        cudaFuncAttributeMaxDynamicSharedMemorySize, SMEM_NN);
    cudaFuncSetAttribute(mma_nt_scores, cudaFuncAttributeMaxDynamicSharedMemorySize, SMEM_NT);

    // 0. pre-round weights to tf32 format
    {
        auto cvt = [](const float* in, float* outp, long n) {
            int n4 = (int)(n / 4);
            cvt_tf32_kernel<<<(n4 + 255) / 256, 256>>>((const float4*)in, (float4*)outp, n4);
        };
        cvt(Wq, cWq, (long)H_*C_*D_);
        cvt(Wk, cWk, (long)H_*C_*D_);
        cvt(Wv, cWv, (long)H_*C_*D_);
        cvt(Wo, cWo, (long)HD_*C_);
        cvt(W1, cW1, (long)C_*FF_);
        cvt(W2, cW2, (long)FF_*C_);
        cvt(Wlm, cWlm, (long)C_*V_);
    }

    // 1. embedding
    embed_kernel<<<(B_*T_*C_)/256, 256>>>(idx, tok, pos);

    // 2. LN1
    ln_kernel<<<B_*T_, 256>>>(x, h, g1, be1);

    // 3. q,k,v projections
    {
        dim3 grid(D_/128, T_/128, B_*H_);
        long sAb = (long)T_*C_, sBh = (long)C_*D_;
        long sCb = (long)H_*T_*D_, sCh = (long)T_*D_;
        mma_nn<<<grid, 128, SMEM_NN>>>(h, cWq, q, C_, C_, D_, D_,
                              sAb, 0, 0, sBh, sCb, sCh, H_, nullptr, 1.f, F_TF32);
        mma_nn<<<grid, 128, SMEM_NN>>>(h, cWk, k, C_, C_, D_, D_,
                              sAb, 0, 0, sBh, sCb, sCh, H_, nullptr, 1.f, F_TF32);
        mma_nn<<<grid, 128, SMEM_NN>>>(h, cWv, v, C_, C_, D_, D_,
                              sAb, 0, 0, sBh, sCb, sCh, H_, nullptr, 1.f, F_TF32);
    }

    // 4. scores
    {
        dim3 grid(T_/128, T_/128, B_*H_);
        mma_nt_scores<<<grid, 128, SMEM_NT>>>(q, k, wei, D_, D_, D_, T_,
                                     (long)T_*D_, (long)T_*D_, (long)T_*T_,
                                     rsqrtf((float)D_));
    }

    // 5. softmax
    softmax_kernel<<<B_*H_*T_, 256>>>(wei);

    // 6. att = wei @ v  ([B,T,H*D] layout, causal K-limit)
    {
        dim3 grid(D_/128, T_/128, B_*H_);
        mma_nn<<<grid, 128, SMEM_NN>>>(wei, v, att, T_, T_, D_, HD_,
                              (long)H_*T_*T_, (long)T_*T_,
                              (long)H_*T_*D_, (long)T_*D_,
                              (long)T_*HD_, (long)D_, H_,
                              nullptr, 1.f, F_CAUSALK | F_TF32);
    }

    // 7. x += att @ Wo + bo
    mma_nn<<<dim3(C_/128, (B_*T_)/128, 1), 128, SMEM_NN>>>(
        att, cWo, x, HD_, HD_, C_, C_,
        0, 0, 0, 0, 0, 0, 1, bo, 1.f, F_BIAS | F_ADDC);

    // 8. LN2
    ln_kernel<<<B_*T_, 256>>>(x, h, g2, be2);

    // 9. ffn = relu(h @ W1 + b1)
    mma_nn<<<dim3(FF_/128, (B_*T_)/128, 1), 128, SMEM_NN>>>(
        h, cW1, ffn, C_, C_, FF_, FF_,
        0, 0, 0, 0, 0, 0, 1, b1, 1.f, F_BIAS | F_RELU | F_TF32);

    // 10. x += ffn @ W2 + b2
    mma_nn<<<dim3(C_/128, (B_*T_)/128, 1), 128, SMEM_NN>>>(
        ffn, cW2, x, FF_, FF_, C_, C_,
        0, 0, 0, 0, 0, 0, 1, b2, 1.f, F_BIAS | F_ADDC);

    // 11. final LN
    ln_kernel<<<B_*T_, 256>>>(x, h, gf, bef);

    // 12. logits = h @ Wlm + blm
    mma_nn<<<dim3(V_/128, (B_*T_)/128, 1), 128, SMEM_NN>>>(
        h, cWlm, out, C_, C_, V_, V_,
        0, 0, 0, 0, 0, 0, 1, blm, 1.f, F_BIAS);
}

// round 13
// speedup vs baseline: 1.2448x; 1.0053x over previous
#include <cuda_runtime.h>
#include <cuda_bf16.h>
#include <math.h>

// Problem constants
#define B_ 2
#define T_ 2048
#define C_ 1024
#define H_ 8
#define D_ 1024
#define V_ 32000
#define HD_ (H_*D_)
#define FF_ (4*C_)

// Scratch (device globals; no dynamic allocation allowed)
__device__ float g_x  [B_*T_*C_];
__device__ float g_h  [B_*T_*C_];
__device__ float g_q  [B_*H_*T_*D_];
__device__ float g_k  [B_*H_*T_*D_];
__device__ float g_v  [B_*H_*T_*D_];
__device__ float g_att[B_*T_*HD_];
__device__ float g_ffn[B_*T_*FF_];
__device__ float g_wei[(size_t)B_*H_*T_*T_];
// tf32-rounded weight copies
__device__ float g_cWq [H_*C_*D_];
__device__ float g_cWk [H_*C_*D_];
__device__ float g_cWv [H_*C_*D_];
__device__ float g_cWo [HD_*C_];
__device__ float g_cW1 [C_*FF_];
__device__ float g_cW2 [FF_*C_];
__device__ float g_cWlm[C_*V_];

#define F_BIAS    1
#define F_ADDC    2
#define F_RELU    4
#define F_CAUSALK 8
#define F_TF32    16
#define F_SWAPXY  32

__device__ __forceinline__ float tf32r(float x) {
    unsigned r;
    asm("cvt.rna.tf32.f32 %0, %1;" : "=r"(r) : "f"(x));
    return __uint_as_float(r);
}

// ---------------------------------------------------------------------------
// Fused weight pre-rounding: one kernel for all 7 weights (float4 segments)
// ---------------------------------------------------------------------------
#define N4_QKV (H_*C_*D_/4)    // 2097152 each
#define N4_WO  (HD_*C_/4)      // 2097152
#define N4_W12 (C_*FF_/4)      // 1048576 each
#define N4_WLM (C_*V_/4)       // 8192000
#define N4_TOT (3*N4_QKV + N4_WO + 2*N4_W12 + N4_WLM)

__global__ void cvt_all_kernel(const float4* __restrict__ wq, const float4* __restrict__ wk,
                               const float4* __restrict__ wv, const float4* __restrict__ wo,
                               const float4* __restrict__ w1, const float4* __restrict__ w2,
                               const float4* __restrict__ wlm,
                               float4* __restrict__ cq, float4* __restrict__ ck,
                               float4* __restrict__ cv, float4* __restrict__ co,
                               float4* __restrict__ c1, float4* __restrict__ c2,
                               float4* __restrict__ clm) {
    long i = blockIdx.x * (long)blockDim.x + threadIdx.x;
    if (i >= N4_TOT) return;
    const float4* src; float4* dst; long off;
    if (i < N4_QKV)                       { src = wq;  dst = cq;  off = i; }
    else if (i < 2L*N4_QKV)               { src = wk;  dst = ck;  off = i - N4_QKV; }
    else if (i < 3L*N4_QKV)               { src = wv;  dst = cv;  off = i - 2L*N4_QKV; }
    else if (i < 3L*N4_QKV + N4_WO)       { src = wo;  dst = co;  off = i - 3L*N4_QKV; }
    else if (i < 3L*N4_QKV + N4_WO + N4_W12)
                                          { src = w1;  dst = c1;  off = i - (3L*N4_QKV + N4_WO); }
    else if (i < 3L*N4_QKV + N4_WO + 2L*N4_W12)
                                          { src = w2;  dst = c2;  off = i - (3L*N4_QKV + N4_WO + N4_W12); }
    else                                  { src = wlm; dst = clm; off = i - (3L*N4_QKV + N4_WO + 2L*N4_W12); }
    float4 v = src[off];
    v.x = tf32r(v.x); v.y = tf32r(v.y); v.z = tf32r(v.z); v.w = tf32r(v.w);
    dst[off] = v;
}

// ---------------------------------------------------------------------------
// Embedding
// ---------------------------------------------------------------------------
__global__ void embed_kernel(const int* __restrict__ idx,
                             const float* __restrict__ tok,
                             const float* __restrict__ pos) {
    int i = blockIdx.x * blockDim.x + threadIdx.x;
    int c  = i % C_;
    int bt = i / C_;
    int t  = bt % T_;
    g_x[i] = tok[(size_t)idx[bt] * C_ + c] + pos[t * C_ + c];
}

// ---------------------------------------------------------------------------
// LayerNorm (C=1024); output tf32-rounded (feeds GEMM operands)
// ---------------------------------------------------------------------------
__global__ void ln_kernel(const float* __restrict__ in, float* __restrict__ out,
                          const float* __restrict__ g, const float* __restrict__ b) {
    int row = blockIdx.x;
    const float* x = in + (size_t)row * C_;
    float* o = out + (size_t)row * C_;
    int tid = threadIdx.x;

    __shared__ float rs[256], rss[256];
    float s = 0.f, ss = 0.f;
    for (int c = tid; c < C_; c += 256) { float v = x[c]; s += v; ss += v * v; }
    rs[tid] = s; rss[tid] = ss;
    __syncthreads();
    for (int off = 128; off > 0; off >>= 1) {
        if (tid < off) { rs[tid] += rs[tid + off]; rss[tid] += rss[tid + off]; }
        __syncthreads();
    }
    float mean = rs[0] * (1.0f / C_);
    float var  = rss[0] * (1.0f / C_) - mean * mean;
    float inv  = rsqrtf(var + 1e-5f);
    for (int c = tid; c < C_; c += 256)
        o[c] = tf32r((x[c] - mean) * inv * g[c] + b[c]);
}

// ---------------------------------------------------------------------------
// Causal softmax; probs tf32-rounded; zero pad up to next 128 boundary
// ---------------------------------------------------------------------------
__global__ void softmax_kernel(float* __restrict__ wei) {
    int row = blockIdx.x;
    int t = row % T_;
    float* w = wei + (size_t)row * T_;
    int n = t + 1;
    int tid = threadIdx.x;
    __shared__ float red[256];

    float m = -1e30f;
    for (int s = tid; s < n; s += 256) m = fmaxf(m, w[s]);
    red[tid] = m;
    __syncthreads();
    for (int off = 128; off > 0; off >>= 1) {
        if (tid < off) red[tid] = fmaxf(red[tid], red[tid + off]);
        __syncthreads();
    }
    m = red[0];
    __syncthreads();

    float sum = 0.f;
    for (int s = tid; s < n; s += 256) { float e = expf(w[s] - m); w[s] = e; sum += e; }
    red[tid] = sum;
    __syncthreads();
    for (int off = 128; off > 0; off >>= 1) {
        if (tid < off) red[tid] += red[tid + off];
        __syncthreads();
    }
    float inv = 1.f / red[0];
    for (int s = tid; s < n; s += 256) w[s] = tf32r(w[s] * inv);

    int nend = (n + 127) & ~127;
    for (int s = n + tid; s < nend; s += 256) w[s] = 0.f;
}

// ---------------------------------------------------------------------------
// mma helpers (operands pre-rounded to tf32 — no cvt in loop)
// ---------------------------------------------------------------------------
__device__ __forceinline__ void mma8(float* d, const unsigned* a, unsigned b0, unsigned b1) {
    asm volatile(
        "mma.sync.aligned.m16n8k8.row.col.f32.tf32.tf32.f32 "
        "{%0,%1,%2,%3}, {%4,%5,%6,%7}, {%8,%9}, {%0,%1,%2,%3};\n"
        : "+f"(d[0]), "+f"(d[1]), "+f"(d[2]), "+f"(d[3])
        : "r"(a[0]), "r"(a[1]), "r"(a[2]), "r"(a[3]), "r"(b0), "r"(b1));
}

__device__ __forceinline__ void cp16(void* s, const void* g) {
    unsigned sa = (unsigned)__cvta_generic_to_shared(s);
    asm volatile("cp.async.cg.shared.global [%0], [%1], 16;\n" :: "r"(sa), "l"(g));
}
__device__ __forceinline__ void cp_commit() {
    asm volatile("cp.async.commit_group;\n" ::);
}
__device__ __forceinline__ unsigned ldu(const float* p) {
    return __float_as_uint(*p);
}

// A-style tile: [128 rows][k, stride 36]  (36 % 32 == 4 -> frag banks 4g+tig, conflict-free)
// B-style tile: [32 k-rows][col, stride 136] (8tig+g -> conflict-free)
#define AP 36
#define BP 136
#define A_W (128*AP)        // floats per A stage (4608)
#define B_W (32*BP)         // floats per B stage (4352)
#define STG_NN (A_W + B_W)  // 8960 floats = 35840 B
#define STG_NT (A_W + A_W)  // 9216 floats = 36864 B
#define SMEM_NN (3*STG_NN*4)
#define SMEM_NT (3*STG_NT*4)

// Warp tile 64x64: 4 m-subtiles x 8 n-subtiles
__device__ __forceinline__ void compute_k8_nn(
    const float (* __restrict__ As)[AP], const float (* __restrict__ Bs)[BP],
    float acc[4][8][4], int kk, int wm, int wn, int g, int tig)
{
    unsigned a[4][4];
#pragma unroll
    for (int mt = 0; mt < 4; mt++) {
        int mrow = wm * 64 + mt * 16;
        a[mt][0] = ldu(&As[mrow + g    ][kk + tig    ]);
        a[mt][1] = ldu(&As[mrow + g + 8][kk + tig    ]);
        a[mt][2] = ldu(&As[mrow + g    ][kk + tig + 4]);
        a[mt][3] = ldu(&As[mrow + g + 8][kk + tig + 4]);
    }
#pragma unroll
    for (int nt = 0; nt < 8; nt++) {
        int ncol = wn * 64 + nt * 8 + g;
        unsigned b0 = ldu(&Bs[kk + tig    ][ncol]);
        unsigned b1 = ldu(&Bs[kk + tig + 4][ncol]);
#pragma unroll
        for (int mt = 0; mt < 4; mt++) mma8(acc[mt][nt], a[mt], b0, b1);
    }
}

__device__ __forceinline__ void compute_k8_nt(
    const float (* __restrict__ As)[AP], const float (* __restrict__ Bt)[AP],
    float acc[4][8][4], int kk, int wm, int wn, int g, int tig)
{
    unsigned a[4][4];
#pragma unroll
    for (int mt = 0; mt < 4; mt++) {
        int mrow = wm * 64 + mt * 16;
        a[mt][0] = ldu(&As[mrow + g    ][kk + tig    ]);
        a[mt][1] = ldu(&As[mrow + g + 8][kk + tig    ]);
        a[mt][2] = ldu(&As[mrow + g    ][kk + tig + 4]);
        a[mt][3] = ldu(&As[mrow + g + 8][kk + tig + 4]);
    }
#pragma unroll
    for (int nt = 0; nt < 8; nt++) {
        int ncol = wn * 64 + nt * 8 + g;
        unsigned b0 = ldu(&Bt[ncol][kk + tig    ]);
        unsigned b1 = ldu(&Bt[ncol][kk + tig + 4]);
#pragma unroll
        for (int mt = 0; mt < 4; mt++) mma8(acc[mt][nt], a[mt], b0, b1);
    }
}

// ---------------------------------------------------------------------------
// tf32 GEMM NN: 128x128 tile, BK=32, 128 threads, 3-stage ring, 1 sync/iter
// F_SWAPXY: bx indexes M tiles (fast axis) for L2 reuse of wide B matrices
// ---------------------------------------------------------------------------
__global__ void __launch_bounds__(128, 2)
mma_nn(const float* __restrict__ A, const float* __restrict__ Bm,
       float* __restrict__ Cm,
       int K, int lda, int ldb, int ldc,
       long sAb, long sAh, long sBb, long sBh, long sCb, long sCh, int batchH,
       const float* __restrict__ bias, float scale, int flags)
{
    extern __shared__ float dsm[];

    int z  = blockIdx.z;
    int zb = z / batchH, zh = z % batchH;
    A  += zb * sAb + zh * sAh;
    Bm += zb * sBb + zh * sBh;
    Cm += zb * sCb + zh * sCh;

    int bx, by;
    if (flags & F_SWAPXY) { bx = blockIdx.y; by = blockIdx.x; }
    else                  { bx = blockIdx.x; by = blockIdx.y; }
    int row0 = by * 128, col0 = bx * 128;

    int Keff = K;
    if (flags & F_CAUSALK) { int kl = (by + 1) * 128; if (kl < Keff) Keff = kl; }

    int tid  = threadIdx.x;
    int lane = tid & 31, warp = tid >> 5;
    int wm = warp >> 1, wn = warp & 1;
    int g  = lane >> 2, tig = lane & 3;

    const float* Ag = A  + (size_t)row0 * lda;
    const float* Bg = Bm + col0;
    int lrow = tid >> 3, lch = (tid & 7) * 4;   // A: 16 rows x 32k per pass, 8 passes
    int brow = tid >> 5, bc = (tid & 31) * 4;   // B: 4 k-rows x 128 cols per pass, 8 passes

    float acc[4][8][4];
#pragma unroll
    for (int i = 0; i < 4; i++)
#pragma unroll
        for (int j = 0; j < 8; j++)
#pragma unroll
            for (int r = 0; r < 4; r++) acc[i][j][r] = 0.f;

    int iters = Keff / 32;

    // prologue: stages 0 and 1
#pragma unroll
    for (int st = 0; st < 2; st++) {
        if (st < iters) {
            float* As = dsm + st * STG_NN;
            float* Bs = As + A_W;
            int k0 = st * 32;
#pragma unroll
            for (int p = 0; p < 8; p++)
                cp16(&As[(lrow + 16 * p) * AP + lch], Ag + (size_t)(lrow + 16 * p) * lda + k0 + lch);
#pragma unroll
            for (int p = 0; p < 8; p++)
                cp16(&Bs[(brow + 4 * p) * BP + bc], Bg + (size_t)(k0 + brow + 4 * p) * ldb + bc);
            cp_commit();
        }
    }

    for (int it = 0; it < iters; ++it) {
        if (it + 1 < iters) asm volatile("cp.async.wait_group 1;\n" ::);
        else                asm volatile("cp.async.wait_group 0;\n" ::);
        __syncthreads();
        if (it + 2 < iters) {
            int st = (it + 2) % 3;
            int k0 = (it + 2) * 32;
            float* As = dsm + st * STG_NN;
            float* Bs = As + A_W;
#pragma unroll
            for (int p = 0; p < 8; p++)
                cp16(&As[(lrow + 16 * p) * AP + lch], Ag + (size_t)(lrow + 16 * p) * lda + k0 + lch);
#pragma unroll
            for (int p = 0; p < 8; p++)
                cp16(&Bs[(brow + 4 * p) * BP + bc], Bg + (size_t)(k0 + brow + 4 * p) * ldb + bc);
            cp_commit();
        }
        const float (*As)[AP] = (const float (*)[AP])(dsm + (it % 3) * STG_NN);
        const float (*Bs)[BP] = (const float (*)[BP])(dsm + (it % 3) * STG_NN + A_W);
        compute_k8_nn(As, Bs, acc, 0,  wm, wn, g, tig);
        compute_k8_nn(As, Bs, acc, 8,  wm, wn, g, tig);
        compute_k8_nn(As, Bs, acc, 16, wm, wn, g, tig);
        compute_k8_nn(As, Bs, acc, 24, wm, wn, g, tig);
    }

    // epilogue
#pragma unroll
    for (int mt = 0; mt < 4; mt++) {
#pragma unroll
        for (int nt = 0; nt < 8; nt++) {
            int r = row0 + wm * 64 + mt * 16 + g;
            int c = col0 + wn * 64 + nt * 8 + tig * 2;
#pragma unroll
            for (int half = 0; half < 2; half++) {
                float* p = Cm + (size_t)(r + 8 * half) * ldc + c;
                float x0 = acc[mt][nt][2*half + 0] * scale;
                float x1 = acc[mt][nt][2*half + 1] * scale;
                if (flags & F_BIAS) { x0 += bias[c]; x1 += bias[c + 1]; }
                if (flags & F_RELU) { x0 = fmaxf(x0, 0.f); x1 = fmaxf(x1, 0.f); }
                if (flags & F_TF32) { x0 = tf32r(x0); x1 = tf32r(x1); }
                if (flags & F_ADDC) { x0 += p[0]; x1 += p[1]; }
                p[0] = x0; p[1] = x1;
            }
        }
    }
}

// ---------------------------------------------------------------------------
// tf32 GEMM NT (scores): 128x128 tile, BK=32; causal tile skip
// ---------------------------------------------------------------------------
__global__ void __launch_bounds__(128, 2)
mma_nt_scores(const float* __restrict__ A, const float* __restrict__ Bm,
              float* __restrict__ Cm,
              int K, int lda, int ldb, int ldc,
              long sA, long sB, long sC, float scale)
{
    int bx = blockIdx.x, by = blockIdx.y;
    if (bx > by) return;

    extern __shared__ float dsm[];

    int z = blockIdx.z;
    A  += (long)z * sA;
    Bm += (long)z * sB;
    Cm += (long)z * sC;

    int row0 = by * 128, col0 = bx * 128;

    int tid  = threadIdx.x;
    int lane = tid & 31, warp = tid >> 5;
    int wm = warp >> 1, wn = warp & 1;
    int g  = lane >> 2, tig = lane & 3;

    const float* Ag = A  + (size_t)row0 * lda;
    const float* Bg = Bm + (size_t)col0 * ldb;
    int lrow = tid >> 3, lch = (tid & 7) * 4;

    float acc[4][8][4];
#pragma unroll
    for (int i = 0; i < 4; i++)
#pragma unroll
        for (int j = 0; j < 8; j++)
#pragma unroll
            for (int r = 0; r < 4; r++) acc[i][j][r] = 0.f;

    int iters = K / 32;

    // prologue: stages 0 and 1
#pragma unroll
    for (int st = 0; st < 2; st++) {
        if (st < iters) {
            float* As = dsm + st * STG_NT;
            float* Bt = As + A_W;
            int k0 = st * 32;
#pragma unroll
            for (int p = 0; p < 8; p++)
                cp16(&As[(lrow + 16 * p) * AP + lch], Ag + (size_t)(lrow + 16 * p) * lda + k0 + lch);
#pragma unroll
            for (int p = 0; p < 8; p++)
                cp16(&Bt[(lrow + 16 * p) * AP + lch], Bg + (size_t)(lrow + 16 * p) * ldb + k0 + lch);
            cp_commit();
        }
    }

    for (int it = 0; it < iters; ++it) {
        if (it + 1 < iters) asm volatile("cp.async.wait_group 1;\n" ::);
        else                asm volatile("cp.async.wait_group 0;\n" ::);
        __syncthreads();
        if (it + 2 < iters) {
            int st = (it + 2) % 3;
            int k0 = (it + 2) * 32;
            float* As = dsm + st * STG_NT;
            float* Bt = As + A_W;
#pragma unroll
            for (int p = 0; p < 8; p++)
                cp16(&As[(lrow + 16 * p) * AP + lch], Ag + (size_t)(lrow + 16 * p) * lda + k0 + lch);
#pragma unroll
            for (int p = 0; p < 8; p++)
                cp16(&Bt[(lrow + 16 * p) * AP + lch], Bg + (size_t)(lrow + 16 * p) * ldb + k0 + lch);
            cp_commit();
        }
        const float (*As)[AP] = (const float (*)[AP])(dsm + (it % 3) * STG_NT);
        const float (*Bt)[AP] = (const float (*)[AP])(dsm + (it % 3) * STG_NT + A_W);
        compute_k8_nt(As, Bt, acc, 0,  wm, wn, g, tig);
        compute_k8_nt(As, Bt, acc, 8,  wm, wn, g, tig);
        compute_k8_nt(As, Bt, acc, 16, wm, wn, g, tig);
        compute_k8_nt(As, Bt, acc, 24, wm, wn, g, tig);
    }

#pragma unroll
    for (int mt = 0; mt < 4; mt++) {
#pragma unroll
        for (int nt = 0; nt < 8; nt++) {
            int r = row0 + wm * 64 + mt * 16 + g;
            int c = col0 + wn * 64 + nt * 8 + tig * 2;
#pragma unroll
            for (int half = 0; half < 2; half++) {
                float* p = Cm + (size_t)(r + 8 * half) * ldc + c;
                p[0] = acc[mt][nt][2*half + 0] * scale;
                p[1] = acc[mt][nt][2*half + 1] * scale;
            }
        }
    }
}

// ---------------------------------------------------------------------------
// Host launch
// ---------------------------------------------------------------------------
extern "C" void kernel_launch(void* const* d_in, const int* in_sizes, int n_in,
                              void* d_out, int out_size) {
    const int*   idx = (const int*)  d_in[0];
    const float* tok = (const float*)d_in[1];
    const float* pos = (const float*)d_in[2];
    const float* Wq  = (const float*)d_in[3];
    const float* Wk  = (const float*)d_in[4];
    const float* Wv  = (const float*)d_in[5];
    const float* Wo  = (const float*)d_in[6];
    const float* bo  = (const float*)d_in[7];
    const float* W1  = (const float*)d_in[8];
    const float* b1  = (const float*)d_in[9];
    const float* W2  = (const float*)d_in[10];
    const float* b2  = (const float*)d_in[11];
    const float* g1  = (const float*)d_in[12];
    const float* be1 = (const float*)d_in[13];
    const float* g2  = (const float*)d_in[14];
    const float* be2 = (const float*)d_in[15];
    const float* gf  = (const float*)d_in[16];
    const float* bef = (const float*)d_in[17];
    const float* Wlm = (const float*)d_in[18];
    const float* blm = (const float*)d_in[19];
    float* out = (float*)d_out;

    float *x, *h, *q, *k, *v, *att, *ffn, *wei;
    float *cWq, *cWk, *cWv, *cWo, *cW1, *cW2, *cWlm;
    cudaGetSymbolAddress((void**)&x,   g_x);
    cudaGetSymbolAddress((void**)&h,   g_h);
    cudaGetSymbolAddress((void**)&q,   g_q);
    cudaGetSymbolAddress((void**)&k,   g_k);
    cudaGetSymbolAddress((void**)&v,   g_v);
    cudaGetSymbolAddress((void**)&att, g_att);
    cudaGetSymbolAddress((void**)&ffn, g_ffn);
    cudaGetSymbolAddress((void**)&wei, g_wei);
    cudaGetSymbolAddress((void**)&cWq, g_cWq);
    cudaGetSymbolAddress((void**)&cWk, g_cWk);
    cudaGetSymbolAddress((void**)&cWv, g_cWv);
    cudaGetSymbolAddress((void**)&cWo, g_cWo);
    cudaGetSymbolAddress((void**)&cW1, g_cW1);
    cudaGetSymbolAddress((void**)&cW2, g_cW2);
    cudaGetSymbolAddress((void**)&cWlm, g_cWlm);

    cudaFuncSetAttribute(mma_nn,        cudaFuncAttributeMaxDynamicSharedMemorySize, SMEM_NN);
    cudaFuncSetAttribute(mma_nt_scores, cudaFuncAttributeMaxDynamicSharedMemorySize, SMEM_NT);

    // 0. pre-round all weights to tf32 format (single fused kernel)
    {
        long blocks = (N4_TOT + 255) / 256;
        cvt_all_kernel<<<(int)blocks, 256>>>(
            (const float4*)Wq, (const float4*)Wk, (const float4*)Wv, (const float4*)Wo,
            (const float4*)W1, (const float4*)W2, (const float4*)Wlm,
            (float4*)cWq, (float4*)cWk, (float4*)cWv, (float4*)cWo,
            (float4*)cW1, (float4*)cW2, (float4*)cWlm);
    }

    // 1. embedding
    embed_kernel<<<(B_*T_*C_)/256, 256>>>(idx, tok, pos);

    // 2. LN1
    ln_kernel<<<B_*T_, 256>>>(x, h, g1, be1);

    // 3. q,k,v projections
    {
        dim3 grid(D_/128, T_/128, B_*H_);
        long sAb = (long)T_*C_, sBh = (long)C_*D_;
        long sCb = (long)H_*T_*D_, sCh = (long)T_*D_;
        mma_nn<<<grid, 128, SMEM_NN>>>(h, cWq, q, C_, C_, D_, D_,
                              sAb, 0, 0, sBh, sCb, sCh, H_, nullptr, 1.f, F_TF32);
        mma_nn<<<grid, 128, SMEM_NN>>>(h, cWk, k, C_, C_, D_, D_,
                              sAb, 0, 0, sBh, sCb, sCh, H_, nullptr, 1.f, F_TF32);
        mma_nn<<<grid, 128, SMEM_NN>>>(h, cWv, v, C_, C_, D_, D_,
                              sAb, 0, 0, sBh, sCb, sCh, H_, nullptr, 1.f, F_TF32);
    }

    // 4. scores
    {
        dim3 grid(T_/128, T_/128, B_*H_);
        mma_nt_scores<<<grid, 128, SMEM_NT>>>(q, k, wei, D_, D_, D_, T_,
                                     (long)T_*D_, (long)T_*D_, (long)T_*T_,
                                     rsqrtf((float)D_));
    }

    // 5. softmax
    softmax_kernel<<<B_*H_*T_, 256>>>(wei);

    // 6. att = wei @ v  ([B,T,H*D] layout, causal K-limit)
    {
        dim3 grid(D_/128, T_/128, B_*H_);
        mma_nn<<<grid, 128, SMEM_NN>>>(wei, v, att, T_, T_, D_, HD_,
                              (long)H_*T_*T_, (long)T_*T_,
                              (long)H_*T_*D_, (long)T_*D_,
                              (long)T_*HD_, (long)D_, H_,
                              nullptr, 1.f, F_CAUSALK | F_TF32);
    }

    // 7. x += att @ Wo + bo
    mma_nn<<<dim3(C_/128, (B_*T_)/128, 1), 128, SMEM_NN>>>(
        att, cWo, x, HD_, HD_, C_, C_,
        0, 0, 0, 0, 0, 0, 1, bo, 1.f, F_BIAS | F_ADDC);

    // 8. LN2
    ln_kernel<<<B_*T_, 256>>>(x, h, g2, be2);

    // 9. ffn = relu(h @ W1 + b1)
    mma_nn<<<dim3(FF_/128, (B_*T_)/128, 1), 128, SMEM_NN>>>(
        h, cW1, ffn, C_, C_, FF_, FF_,
        0, 0, 0, 0, 0, 0, 1, b1, 1.f, F_BIAS | F_RELU | F_TF32);

    // 10. x += ffn @ W2 + b2
    mma_nn<<<dim3(C_/128, (B_*T_)/128, 1), 128, SMEM_NN>>>(
        ffn, cW2, x, FF_, FF_, C_, C_,
        0, 0, 0, 0, 0, 0, 1, b2, 1.f, F_BIAS | F_ADDC);

    // 11. final LN
    ln_kernel<<<B_*T_, 256>>>(x, h, gf, bef);

    // 12. logits = h @ Wlm + blm — M-tiles on fast axis (F_SWAPXY) so each
    // Wlm stripe is consumed by all 32 M-tiles within one wave (L2 reuse)
    mma_nn<<<dim3((B_*T_)/128, V_/128, 1), 128, SMEM_NN>>>(
        h, cWlm, out, C_, C_, V_, V_,
        0, 0, 0, 0, 0, 0, 1, blm, 1.f, F_BIAS | F_SWAPXY);
}

// round 14
// speedup vs baseline: 1.9812x; 1.5917x over previous
#include <cuda_runtime.h>
#include <cuda_fp16.h>
#include <math.h>

// Problem constants
#define B_ 2
#define T_ 2048
#define C_ 1024
#define H_ 8
#define D_ 1024
#define V_ 32000
#define HD_ (H_*D_)
#define FF_ (4*C_)

// fp32 buffers
__device__ float  g_x  [B_*T_*C_];                 // residual stream
__device__ float  g_wei[(size_t)B_*H_*T_*T_];      // raw scores (fp32 for softmax)
// fp16 operand buffers
__device__ __half g_hh [B_*T_*C_];                 // LN output
__device__ __half g_qh [B_*H_*T_*D_];
__device__ __half g_kh [B_*H_*T_*D_];
__device__ __half g_vth[B_*H_*D_*T_];              // v transposed [b,h,D,T]
__device__ __half g_ath[B_*T_*HD_];                // attention out
__device__ __half g_fh [B_*T_*FF_];                // ffn hidden
__device__ __half g_ph [(size_t)B_*H_*T_*T_];      // softmax probs
// transposed fp16 weights ([N,K] layouts)
__device__ __half g_WqT [H_*D_*C_];
__device__ __half g_WkT [H_*D_*C_];
__device__ __half g_WvT [H_*D_*C_];
__device__ __half g_WoT [C_*HD_];
__device__ __half g_W1T [FF_*C_];
__device__ __half g_W2T [C_*FF_];
__device__ __half g_WlmT[(size_t)V_*C_];

#define F_BIAS    1
#define F_ADDC    2
#define F_RELU    4
#define F_CAUSALK 8
#define F_OUTH    16
#define F_SWAPXY  32
#define F_CSKIP   64

// ---------------------------------------------------------------------------
// Transpose + fp16 convert: out[Cc][R] = half(in[R][Cc]^T), batched over z
// ---------------------------------------------------------------------------
__global__ void transH_kernel(const float* __restrict__ in, __half* __restrict__ out,
                              int R, int Cc, long sIn, long sOut) {
    __shared__ float t[32][33];
    in  += (long)blockIdx.z * sIn;
    out += (long)blockIdx.z * sOut;
    int c0 = blockIdx.x * 32, r0 = blockIdx.y * 32;
    int x = threadIdx.x, y = threadIdx.y;   // 32 x 8
#pragma unroll
    for (int j = 0; j < 32; j += 8)
        t[y + j][x] = in[(size_t)(r0 + y + j) * Cc + c0 + x];
    __syncthreads();
#pragma unroll
    for (int j = 0; j < 32; j += 8)
        out[(size_t)(c0 + y + j) * R + r0 + x] = __float2half_rn(t[x][y + j]);
}

// ---------------------------------------------------------------------------
// Embedding (fp32 residual)
// ---------------------------------------------------------------------------
__global__ void embed_kernel(const int* __restrict__ idx,
                             const float* __restrict__ tok,
                             const float* __restrict__ pos) {
    int i = blockIdx.x * blockDim.x + threadIdx.x;
    int c  = i % C_;
    int bt = i / C_;
    int t  = bt % T_;
    g_x[i] = tok[(size_t)idx[bt] * C_ + c] + pos[t * C_ + c];
}

// ---------------------------------------------------------------------------
// LayerNorm: fp32 in -> fp16 out (feeds GEMM operands)
// ---------------------------------------------------------------------------
__global__ void ln_kernel(const float* __restrict__ in, __half* __restrict__ out,
                          const float* __restrict__ g, const float* __restrict__ b) {
    int row = blockIdx.x;
    const float* x = in + (size_t)row * C_;
    __half* o = out + (size_t)row * C_;
    int tid = threadIdx.x;

    __shared__ float rs[256], rss[256];
    float s = 0.f, ss = 0.f;
    for (int c = tid; c < C_; c += 256) { float v = x[c]; s += v; ss += v * v; }
    rs[tid] = s; rss[tid] = ss;
    __syncthreads();
    for (int off = 128; off > 0; off >>= 1) {
        if (tid < off) { rs[tid] += rs[tid + off]; rss[tid] += rss[tid + off]; }
        __syncthreads();
    }
    float mean = rs[0] * (1.0f / C_);
    float var  = rss[0] * (1.0f / C_) - mean * mean;
    float inv  = rsqrtf(var + 1e-5f);
    for (int c = tid; c < C_; c += 256)
        o[c] = __float2half_rn((x[c] - mean) * inv * g[c] + b[c]);
}

// ---------------------------------------------------------------------------
// Causal softmax: fp32 scores -> fp16 probs; zero pad to next 128 boundary
// ---------------------------------------------------------------------------
__global__ void softmax_kernel(float* __restrict__ wei, __half* __restrict__ prob) {
    int row = blockIdx.x;
    int t = row % T_;
    float* w = wei + (size_t)row * T_;
    __half* ph = prob + (size_t)row * T_;
    int n = t + 1;
    int tid = threadIdx.x;
    __shared__ float red[256];

    float m = -1e30f;
    for (int s = tid; s < n; s += 256) m = fmaxf(m, w[s]);
    red[tid] = m;
    __syncthreads();
    for (int off = 128; off > 0; off >>= 1) {
        if (tid < off) red[tid] = fmaxf(red[tid], red[tid + off]);
        __syncthreads();
    }
    m = red[0];
    __syncthreads();

    float sum = 0.f;
    for (int s = tid; s < n; s += 256) { float e = expf(w[s] - m); w[s] = e; sum += e; }
    red[tid] = sum;
    __syncthreads();
    for (int off = 128; off > 0; off >>= 1) {
        if (tid < off) red[tid] += red[tid + off];
        __syncthreads();
    }
    float inv = 1.f / red[0];
    for (int s = tid; s < n; s += 256) ph[s] = __float2half_rn(w[s] * inv);

    int nend = (n + 127) & ~127;
    for (int s = n + tid; s < nend; s += 256) ph[s] = __float2half_rn(0.f);
}

// ---------------------------------------------------------------------------
// fp16 mma helpers
// ---------------------------------------------------------------------------
__device__ __forceinline__ void mma16(float* d, const unsigned* a, unsigned b0, unsigned b1) {
    asm volatile(
        "mma.sync.aligned.m16n8k16.row.col.f32.f16.f16.f32 "
        "{%0,%1,%2,%3}, {%4,%5,%6,%7}, {%8,%9}, {%0,%1,%2,%3};\n"
        : "+f"(d[0]), "+f"(d[1]), "+f"(d[2]), "+f"(d[3])
        : "r"(a[0]), "r"(a[1]), "r"(a[2]), "r"(a[3]), "r"(b0), "r"(b1));
}

__device__ __forceinline__ void cp16(void* s, const void* g) {
    unsigned sa = (unsigned)__cvta_generic_to_shared(s);
    asm volatile("cp.async.cg.shared.global [%0], [%1], 16;\n" :: "r"(sa), "l"(g));
}
__device__ __forceinline__ void cp_commit() {
    asm volatile("cp.async.commit_group;\n" ::);
}
__device__ __forceinline__ unsigned ldu32(const __half* p) {
    return *(const unsigned*)p;
}

// Tiles: [128 rows][K=32 halves, stride 40 halves = 20 words]
// 20 ≡ 20 (mod 32): fragment loads hit banks 20g+tig -> all 32 distinct.
#define APH 40
#define A_WH (128*APH)        // halves per operand stage (5120)
#define STG_H (2*A_WH)        // halves per stage (10240 = 20480 B)
#define SMEM_H (3*STG_H*2)    // bytes (61440)

// Warp tile 64x64: 4 m-subtiles x 8 n-subtiles, k16 per call
__device__ __forceinline__ void compute_k16(
    const __half* __restrict__ As, const __half* __restrict__ Bs,
    float acc[4][8][4], int kk, int wm, int wn, int g, int tig)
{
    unsigned a[4][4];
#pragma unroll
    for (int mt = 0; mt < 4; mt++) {
        int mrow = wm * 64 + mt * 16;
        a[mt][0] = ldu32(&As[(size_t)(mrow + g    ) * APH + kk     + 2 * tig]);
        a[mt][1] = ldu32(&As[(size_t)(mrow + g + 8) * APH + kk     + 2 * tig]);
        a[mt][2] = ldu32(&As[(size_t)(mrow + g    ) * APH + kk + 8 + 2 * tig]);
        a[mt][3] = ldu32(&As[(size_t)(mrow + g + 8) * APH + kk + 8 + 2 * tig]);
    }
#pragma unroll
    for (int nt = 0; nt < 8; nt++) {
        int ncol = wn * 64 + nt * 8 + g;
        unsigned b0 = ldu32(&Bs[(size_t)ncol * APH + kk     + 2 * tig]);
        unsigned b1 = ldu32(&Bs[(size_t)ncol * APH + kk + 8 + 2 * tig]);
#pragma unroll
        for (int mt = 0; mt < 4; mt++) mma16(acc[mt][nt], a[mt], b0, b1);
    }
}

// ---------------------------------------------------------------------------
// Unified fp16 NT GEMM: C[M,N] (+)= scale * A[M,K] @ B[N,K]^T
// 128x128 tile, BK=32, 128 threads, 3-stage ring, 1 sync/iter, 2 CTAs/SM
// ---------------------------------------------------------------------------
__global__ void __launch_bounds__(128, 2)
mma_h(const __half* __restrict__ A, const __half* __restrict__ Bm,
      void* __restrict__ Cout,
      int K, int lda, int ldb, int ldc,
      long sAb, long sAh, long sBb, long sBh, long sCb, long sCh, int batchH,
      const float* __restrict__ bias, float scale, int flags)
{
    extern __shared__ __half hsm[];

    int bx, by;
    if (flags & F_SWAPXY) { bx = blockIdx.y; by = blockIdx.x; }
    else                  { bx = blockIdx.x; by = blockIdx.y; }
    if ((flags & F_CSKIP) && bx > by) return;

    int z  = blockIdx.z;
    int zb = z / batchH, zh = z % batchH;
    A  += zb * sAb + zh * sAh;
    Bm += zb * sBb + zh * sBh;
    long coff = zb * sCb + zh * sCh;

    int row0 = by * 128, col0 = bx * 128;

    int Keff = K;
    if (flags & F_CAUSALK) { int kl = (by + 1) * 128; if (kl < Keff) Keff = kl; }

    int tid  = threadIdx.x;
    int lane = tid & 31, warp = tid >> 5;
    int wm = warp >> 1, wn = warp & 1;
    int g  = lane >> 2, tig = lane & 3;

    const __half* Ag = A  + (size_t)row0 * lda;
    const __half* Bg = Bm + (size_t)col0 * ldb;

    float acc[4][8][4];
#pragma unroll
    for (int i = 0; i < 4; i++)
#pragma unroll
        for (int j = 0; j < 8; j++)
#pragma unroll
            for (int r = 0; r < 4; r++) acc[i][j][r] = 0.f;

    int iters = Keff / 32;

    // prologue: stages 0 and 1 (each thread: 4 chunk-pairs per stage)
#pragma unroll
    for (int st = 0; st < 2; st++) {
        if (st < iters) {
            __half* As = hsm + st * STG_H;
            __half* Bs = As + A_WH;
            int k0 = st * 32;
#pragma unroll
            for (int p = 0; p < 4; p++) {
                int c = p * 128 + tid;
                int row = c >> 2, ch = (c & 3) * 8;
                cp16(&As[(size_t)row * APH + ch], Ag + (size_t)row * lda + k0 + ch);
                cp16(&Bs[(size_t)row * APH + ch], Bg + (size_t)row * ldb + k0 + ch);
            }
            cp_commit();
        }
    }

    for (int it = 0; it < iters; ++it) {
        if (it + 1 < iters) asm volatile("cp.async.wait_group 1;\n" ::);
        else                asm volatile("cp.async.wait_group 0;\n" ::);
        __syncthreads();
        if (it + 2 < iters) {
            int st = (it + 2) % 3;
            int k0 = (it + 2) * 32;
            __half* As = hsm + st * STG_H;
            __half* Bs = As + A_WH;
#pragma unroll
            for (int p = 0; p < 4; p++) {
                int c = p * 128 + tid;
                int row = c >> 2, ch = (c & 3) * 8;
                cp16(&As[(size_t)row * APH + ch], Ag + (size_t)row * lda + k0 + ch);
                cp16(&Bs[(size_t)row * APH + ch], Bg + (size_t)row * ldb + k0 + ch);
            }
            cp_commit();
        }
        const __half* As = hsm + (it % 3) * STG_H;
        const __half* Bs = As + A_WH;
        compute_k16(As, Bs, acc, 0,  wm, wn, g, tig);
        compute_k16(As, Bs, acc, 16, wm, wn, g, tig);
    }

    // epilogue
#pragma unroll
    for (int mt = 0; mt < 4; mt++) {
#pragma unroll
        for (int nt = 0; nt < 8; nt++) {
            int r = row0 + wm * 64 + mt * 16 + g;
            int c = col0 + wn * 64 + nt * 8 + tig * 2;
#pragma unroll
            for (int half_ = 0; half_ < 2; half_++) {
                int rr = r + 8 * half_;
                float x0 = acc[mt][nt][2*half_ + 0] * scale;
                float x1 = acc[mt][nt][2*half_ + 1] * scale;
                if (flags & F_BIAS) { x0 += bias[c]; x1 += bias[c + 1]; }
                if (flags & F_RELU) { x0 = fmaxf(x0, 0.f); x1 = fmaxf(x1, 0.f); }
                if (flags & F_OUTH) {
                    __half2 hv;
                    hv.x = __float2half_rn(x0);
                    hv.y = __float2half_rn(x1);
                    *(__half2*)((__half*)Cout + coff + (size_t)rr * ldc + c) = hv;
                } else {
                    float* p = (float*)Cout + coff + (size_t)rr * ldc + c;
                    if (flags & F_ADDC) { x0 += p[0]; x1 += p[1]; }
                    p[0] = x0; p[1] = x1;
                }
            }
        }
    }
}

// ---------------------------------------------------------------------------
// Host launch
// ---------------------------------------------------------------------------
extern "C" void kernel_launch(void* const* d_in, const int* in_sizes, int n_in,
                              void* d_out, int out_size) {
    const int*   idx = (const int*)  d_in[0];
    const float* tok = (const float*)d_in[1];
    const float* pos = (const float*)d_in[2];
    const float* Wq  = (const float*)d_in[3];
    const float* Wk  = (const float*)d_in[4];
    const float* Wv  = (const float*)d_in[5];
    const float* Wo  = (const float*)d_in[6];
    const float* bo  = (const float*)d_in[7];
    const float* W1  = (const float*)d_in[8];
    const float* b1  = (const float*)d_in[9];
    const float* W2  = (const float*)d_in[10];
    const float* b2  = (const float*)d_in[11];
    const float* g1  = (const float*)d_in[12];
    const float* be1 = (const float*)d_in[13];
    const float* g2  = (const float*)d_in[14];
    const float* be2 = (const float*)d_in[15];
    const float* gf  = (const float*)d_in[16];
    const float* bef = (const float*)d_in[17];
    const float* Wlm = (const float*)d_in[18];
    const float* blm = (const float*)d_in[19];
    float* out = (float*)d_out;

    float  *x, *wei;
    __half *hh, *qh, *kh, *vth, *ath, *fh, *ph;
    __half *WqT, *WkT, *WvT, *WoT, *W1T, *W2T, *WlmT;
    cudaGetSymbolAddress((void**)&x,    g_x);
    cudaGetSymbolAddress((void**)&wei,  g_wei);
    cudaGetSymbolAddress((void**)&hh,   g_hh);
    cudaGetSymbolAddress((void**)&qh,   g_qh);
    cudaGetSymbolAddress((void**)&kh,   g_kh);
    cudaGetSymbolAddress((void**)&vth,  g_vth);
    cudaGetSymbolAddress((void**)&ath,  g_ath);
    cudaGetSymbolAddress((void**)&fh,   g_fh);
    cudaGetSymbolAddress((void**)&ph,   g_ph);
    cudaGetSymbolAddress((void**)&WqT,  g_WqT);
    cudaGetSymbolAddress((void**)&WkT,  g_WkT);
    cudaGetSymbolAddress((void**)&WvT,  g_WvT);
    cudaGetSymbolAddress((void**)&WoT,  g_WoT);
    cudaGetSymbolAddress((void**)&W1T,  g_W1T);
    cudaGetSymbolAddress((void**)&W2T,  g_W2T);
    cudaGetSymbolAddress((void**)&WlmT, g_WlmT);

    cudaFuncSetAttribute(mma_h, cudaFuncAttributeMaxDynamicSharedMemorySize, SMEM_H);

    dim3 tb(32, 8);
    // 0. transpose + fp16-convert all weights
    transH_kernel<<<dim3(D_/32,  C_/32,  H_), tb>>>(Wq,  WqT,  C_,  D_,  (long)C_*D_, (long)D_*C_);
    transH_kernel<<<dim3(D_/32,  C_/32,  H_), tb>>>(Wk,  WkT,  C_,  D_,  (long)C_*D_, (long)D_*C_);
    transH_kernel<<<dim3(D_/32,  C_/32,  H_), tb>>>(Wv,  WvT,  C_,  D_,  (long)C_*D_, (long)D_*C_);
    transH_kernel<<<dim3(C_/32,  HD_/32, 1),  tb>>>(Wo,  WoT,  HD_, C_,  0, 0);
    transH_kernel<<<dim3(FF_/32, C_/32,  1),  tb>>>(W1,  W1T,  C_,  FF_, 0, 0);
    transH_kernel<<<dim3(C_/32,  FF_/32, 1),  tb>>>(W2,  W2T,  FF_, C_,  0, 0);
    transH_kernel<<<dim3(V_/32,  C_/32,  1),  tb>>>(Wlm, WlmT, C_,  V_,  0, 0);

    // 1. embedding
    embed_kernel<<<(B_*T_*C_)/256, 256>>>(idx, tok, pos);

    // 2. LN1 -> fp16
    ln_kernel<<<B_*T_, 256>>>(x, hh, g1, be1);

    // 3. q = h @ WqT^T, k likewise (fp16 out)
    {
        dim3 grid(D_/128, T_/128, B_*H_);
        mma_h<<<grid, 128, SMEM_H>>>(hh, WqT, qh, C_, C_, C_, D_,
            (long)T_*C_, 0, 0, (long)D_*C_, (long)H_*T_*D_, (long)T_*D_, H_,
            nullptr, 1.f, F_OUTH);
        mma_h<<<grid, 128, SMEM_H>>>(hh, WkT, kh, C_, C_, C_, D_,
            (long)T_*C_, 0, 0, (long)D_*C_, (long)H_*T_*D_, (long)T_*D_, H_,
            nullptr, 1.f, F_OUTH);
    }
    // 3b. vt[b,h,D,T] = WvT[D,C] @ h[T,C]^T (fp16 out)
    {
        dim3 grid(T_/128, D_/128, B_*H_);
        mma_h<<<grid, 128, SMEM_H>>>(WvT, hh, vth, C_, C_, C_, T_,
            0, (long)D_*C_, (long)T_*C_, 0, (long)H_*D_*T_, (long)D_*T_, H_,
            nullptr, 1.f, F_OUTH);
    }

    // 4. scores = q @ k^T * D^-0.5 (fp32 out, causal tile skip)
    {
        dim3 grid(T_/128, T_/128, B_*H_);
        mma_h<<<grid, 128, SMEM_H>>>(qh, kh, wei, D_, D_, D_, T_,
            (long)H_*T_*D_, (long)T_*D_, (long)H_*T_*D_, (long)T_*D_,
            (long)H_*T_*T_, (long)T_*T_, H_,
            nullptr, rsqrtf((float)D_), F_CSKIP);
    }

    // 5. softmax: fp32 scores -> fp16 probs (pad to 128)
    softmax_kernel<<<B_*H_*T_, 256>>>(wei, ph);

    // 6. att = probs @ vt^T -> [B,T,HD] fp16, causal K-limit
    {
        dim3 grid(D_/128, T_/128, B_*H_);
        mma_h<<<grid, 128, SMEM_H>>>(ph, vth, ath, T_, T_, T_, HD_,
            (long)H_*T_*T_, (long)T_*T_, (long)H_*D_*T_, (long)D_*T_,
            (long)T_*HD_, (long)D_, H_,
            nullptr, 1.f, F_CAUSALK | F_OUTH);
    }

    // 7. x += att @ WoT^T + bo (fp32)
    mma_h<<<dim3(C_/128, (B_*T_)/128, 1), 128, SMEM_H>>>(
        ath, WoT, x, HD_, HD_, HD_, C_,
        0, 0, 0, 0, 0, 0, 1, bo, 1.f, F_BIAS | F_ADDC);

    // 8. LN2 -> fp16
    ln_kernel<<<B_*T_, 256>>>(x, hh, g2, be2);

    // 9. ffn = relu(h @ W1T^T + b1) (fp16 out)
    mma_h<<<dim3(FF_/128, (B_*T_)/128, 1), 128, SMEM_H>>>(
        hh, W1T, fh, C_, C_, C_, FF_,
        0, 0, 0, 0, 0, 0, 1, b1, 1.f, F_BIAS | F_RELU | F_OUTH);

    // 10. x += ffn @ W2T^T + b2 (fp32)
    mma_h<<<dim3(C_/128, (B_*T_)/128, 1), 128, SMEM_H>>>(
        fh, W2T, x, FF_, FF_, FF_, C_,
        0, 0, 0, 0, 0, 0, 1, b2, 1.f, F_BIAS | F_ADDC);

    // 11. final LN -> fp16
    ln_kernel<<<B_*T_, 256>>>(x, hh, gf, bef);

    // 12. logits = h @ WlmT^T + blm (fp32 out, M-tiles on fast axis for L2 reuse)
    mma_h<<<dim3((B_*T_)/128, V_/128, 1), 128, SMEM_H>>>(
        hh, WlmT, out, C_, C_, C_, V_,
        0, 0, 0, 0, 0, 0, 1, blm, 1.f, F_BIAS | F_SWAPXY);
}

// round 15
// speedup vs baseline: 2.0103x; 1.0147x over previous
#include <cuda_runtime.h>
#include <cuda_fp16.h>
#include <math.h>

// Problem constants
#define B_ 2
#define T_ 2048
#define C_ 1024
#define H_ 8
#define D_ 1024
#define V_ 32000
#define HD_ (H_*D_)
#define FF_ (4*C_)

// fp32 buffers
__device__ float  g_x  [B_*T_*C_];                 // residual stream
__device__ float  g_wei[(size_t)B_*H_*T_*T_];      // raw scores (fp32 for softmax)
// fp16 operand buffers
__device__ __half g_hh [B_*T_*C_];                 // LN output
__device__ __half g_qh [B_*H_*T_*D_];
__device__ __half g_kh [B_*H_*T_*D_];
__device__ __half g_vth[B_*H_*D_*T_];              // v transposed [b,h,D,T]
__device__ __half g_ath[B_*T_*HD_];                // attention out
__device__ __half g_fh [B_*T_*FF_];                // ffn hidden
__device__ __half g_ph [(size_t)B_*H_*T_*T_];      // softmax probs
// transposed fp16 weights ([N,K] layouts)
__device__ __half g_WqT [H_*D_*C_];
__device__ __half g_WkT [H_*D_*C_];
__device__ __half g_WvT [H_*D_*C_];
__device__ __half g_WoT [C_*HD_];
__device__ __half g_W1T [FF_*C_];
__device__ __half g_W2T [C_*FF_];
__device__ __half g_WlmT[(size_t)V_*C_];

#define F_BIAS    1
#define F_ADDC    2
#define F_RELU    4
#define F_CAUSALK 8
#define F_OUTH    16
#define F_SWAPXY  32
#define F_CSKIP   64

// ---------------------------------------------------------------------------
// Fused transpose + fp16 convert for ALL weights: flat 1D grid, 32x32 tiles.
// Segment table (tiles): qkv 3x8192, Wo 8192, W1 4096, W2 4096, Wlm 32000.
// ---------------------------------------------------------------------------
#define TQ_  8192     // per qkv weight (32x32 tiles x 8 heads)
#define TWO_ 8192     // (C/32)x(HD/32)
#define TW1_ 4096     // (FF/32)x(C/32)
#define TW2_ 4096     // (C/32)x(FF/32)
#define TLM_ 32000    // (V/32)x(C/32)
#define T_TOT (3*TQ_ + TWO_ + TW1_ + TW2_ + TLM_)

struct TransArgs {
    const float* Wq; const float* Wk; const float* Wv; const float* Wo;
    const float* W1; const float* W2; const float* Wlm;
    __half* cq; __half* ck; __half* cv; __half* co;
    __half* c1; __half* c2; __half* clm;
};

__global__ void trans_all_kernel(TransArgs args) {
    __shared__ float t[32][33];
    int tidx = blockIdx.x;
    const float* in; __half* out; int R, Cc;
    if (tidx < 3 * TQ_) {
        int w = tidx / TQ_, rem = tidx % TQ_;
        int hd = rem / 1024, tile = rem % 1024;
        const float* src = (w == 0) ? args.Wq : (w == 1) ? args.Wk : args.Wv;
        __half* dst = (w == 0) ? args.cq : (w == 1) ? args.ck : args.cv;
        in = src + (long)hd * C_ * D_;  out = dst + (long)hd * D_ * C_;
        R = C_; Cc = D_; tidx = tile;
    } else if (tidx < 3 * TQ_ + TWO_) {
        in = args.Wo; out = args.co; R = HD_; Cc = C_; tidx -= 3 * TQ_;
    } else if (tidx < 3 * TQ_ + TWO_ + TW1_) {
        in = args.W1; out = args.c1; R = C_; Cc = FF_; tidx -= 3 * TQ_ + TWO_;
    } else if (tidx < 3 * TQ_ + TWO_ + TW1_ + TW2_) {
        in = args.W2; out = args.c2; R = FF_; Cc = C_; tidx -= 3 * TQ_ + TWO_ + TW1_;
    } else {
        in = args.Wlm; out = args.clm; R = C_; Cc = V_; tidx -= 3 * TQ_ + TWO_ + TW1_ + TW2_;
    }
    int ntx = Cc / 32;
    int c0 = (tidx % ntx) * 32, r0 = (tidx / ntx) * 32;
    int x = threadIdx.x, y = threadIdx.y;   // 32 x 8
#pragma unroll
    for (int j = 0; j < 32; j += 8)
        t[y + j][x] = in[(size_t)(r0 + y + j) * Cc + c0 + x];
    __syncthreads();
#pragma unroll
    for (int j = 0; j < 32; j += 8)
        out[(size_t)(c0 + y + j) * R + r0 + x] = __float2half_rn(t[x][y + j]);
}

// ---------------------------------------------------------------------------
// Embedding (fp32 residual)
// ---------------------------------------------------------------------------
__global__ void embed_kernel(const int* __restrict__ idx,
                             const float* __restrict__ tok,
                             const float* __restrict__ pos) {
    int i = blockIdx.x * blockDim.x + threadIdx.x;
    int c  = i % C_;
    int bt = i / C_;
    int t  = bt % T_;
    g_x[i] = tok[(size_t)idx[bt] * C_ + c] + pos[t * C_ + c];
}

// ---------------------------------------------------------------------------
// LayerNorm: fp32 in -> fp16 out
// ---------------------------------------------------------------------------
__global__ void ln_kernel(const float* __restrict__ in, __half* __restrict__ out,
                          const float* __restrict__ g, const float* __restrict__ b) {
    int row = blockIdx.x;
    const float* x = in + (size_t)row * C_;
    __half* o = out + (size_t)row * C_;
    int tid = threadIdx.x;

    __shared__ float rs[256], rss[256];
    float s = 0.f, ss = 0.f;
    for (int c = tid; c < C_; c += 256) { float v = x[c]; s += v; ss += v * v; }
    rs[tid] = s; rss[tid] = ss;
    __syncthreads();
    for (int off = 128; off > 0; off >>= 1) {
        if (tid < off) { rs[tid] += rs[tid + off]; rss[tid] += rss[tid + off]; }
        __syncthreads();
    }
    float mean = rs[0] * (1.0f / C_);
    float var  = rss[0] * (1.0f / C_) - mean * mean;
    float inv  = rsqrtf(var + 1e-5f);
    for (int c = tid; c < C_; c += 256)
        o[c] = __float2half_rn((x[c] - mean) * inv * g[c] + b[c]);
}

// ---------------------------------------------------------------------------
// Causal softmax: fp32 scores -> fp16 probs; zero pad to next 128 boundary
// ---------------------------------------------------------------------------
__global__ void softmax_kernel(float* __restrict__ wei, __half* __restrict__ prob) {
    int row = blockIdx.x;
    int t = row % T_;
    float* w = wei + (size_t)row * T_;
    __half* ph = prob + (size_t)row * T_;
    int n = t + 1;
    int tid = threadIdx.x;
    __shared__ float red[256];

    float m = -1e30f;
    for (int s = tid; s < n; s += 256) m = fmaxf(m, w[s]);
    red[tid] = m;
    __syncthreads();
    for (int off = 128; off > 0; off >>= 1) {
        if (tid < off) red[tid] = fmaxf(red[tid], red[tid + off]);
        __syncthreads();
    }
    m = red[0];
    __syncthreads();

    float sum = 0.f;
    for (int s = tid; s < n; s += 256) { float e = expf(w[s] - m); w[s] = e; sum += e; }
    red[tid] = sum;
    __syncthreads();
    for (int off = 128; off > 0; off >>= 1) {
        if (tid < off) red[tid] += red[tid + off];
        __syncthreads();
    }
    float inv = 1.f / red[0];
    for (int s = tid; s < n; s += 256) ph[s] = __float2half_rn(w[s] * inv);

    int nend = (n + 127) & ~127;
    for (int s = n + tid; s < nend; s += 256) ph[s] = __float2half_rn(0.f);
}

// ---------------------------------------------------------------------------
// fp16 mma + ldmatrix helpers
// ---------------------------------------------------------------------------
__device__ __forceinline__ void mma16(float* d, const unsigned* a, unsigned b0, unsigned b1) {
    asm volatile(
        "mma.sync.aligned.m16n8k16.row.col.f32.f16.f16.f32 "
        "{%0,%1,%2,%3}, {%4,%5,%6,%7}, {%8,%9}, {%0,%1,%2,%3};\n"
        : "+f"(d[0]), "+f"(d[1]), "+f"(d[2]), "+f"(d[3])
        : "r"(a[0]), "r"(a[1]), "r"(a[2]), "r"(a[3]), "r"(b0), "r"(b1));
}

__device__ __forceinline__ void ldsm4(unsigned& r0, unsigned& r1, unsigned& r2, unsigned& r3,
                                      unsigned addr) {
    asm volatile("ldmatrix.sync.aligned.m8n8.x4.shared.b16 {%0,%1,%2,%3}, [%4];"
                 : "=r"(r0), "=r"(r1), "=r"(r2), "=r"(r3) : "r"(addr));
}

__device__ __forceinline__ void cp16(void* s, const void* g) {
    unsigned sa = (unsigned)__cvta_generic_to_shared(s);
    asm volatile("cp.async.cg.shared.global [%0], [%1], 16;\n" :: "r"(sa), "l"(g));
}
__device__ __forceinline__ void cp_commit() {
    asm volatile("cp.async.commit_group;\n" ::);
}

// Tiles: [128 rows][K=32 halves, stride 40 halves = 80 B]
// ldmatrix phases read 8 rows x 16B; banks (20*r)%32 all distinct -> conflict-free
#define APH 40
#define A_WH (128*APH)          // halves per operand stage (5120)
#define STG_H (2*A_WH)          // halves per stage
#define STG_BYTES (STG_H*2)     // 20480
#define SMEM_H (3*STG_BYTES)    // 61440

// Warp tile 64x64: 4 m-subtiles x 8 n-subtiles; fragments via ldmatrix.x4
__device__ __forceinline__ void compute_k16(
    unsigned As, unsigned Bs, float acc[4][8][4],
    int kk, int wm, int wn, int lane)
{
    // A lane pattern: rows (lane&15), k + 8*(lane>>4)
    unsigned aoff = As + (((lane & 15) * APH + ((lane >> 4) << 3) + kk) << 1);
    unsigned a[4][4];
#pragma unroll
    for (int mt = 0; mt < 4; mt++)
        ldsm4(a[mt][0], a[mt][1], a[mt][2], a[mt][3],
              aoff + ((wm * 64 + mt * 16) * APH << 1));

    // B lane pattern: rows (lane&7) + ((lane&16)>>1), k + ((lane&8)?8:0)
    unsigned boff = Bs + ((((lane & 7) + ((lane & 16) >> 1)) * APH
                           + ((lane & 8) ? 8 : 0) + kk) << 1);
#pragma unroll
    for (int ntp = 0; ntp < 4; ntp++) {
        unsigned b0, b1, b2, b3;
        ldsm4(b0, b1, b2, b3, boff + ((wn * 64 + ntp * 16) * APH << 1));
#pragma unroll
        for (int mt = 0; mt < 4; mt++) mma16(acc[mt][2 * ntp    ], a[mt], b0, b1);
#pragma unroll
        for (int mt = 0; mt < 4; mt++) mma16(acc[mt][2 * ntp + 1], a[mt], b2, b3);
    }
}

// ---------------------------------------------------------------------------
// Unified fp16 NT GEMM: C[M,N] (+)= scale * A[M,K] @ B[N,K]^T
// 128x128 tile, BK=32, 128 threads, 3-stage ring, 1 sync/iter, 2 CTAs/SM
// ---------------------------------------------------------------------------
__global__ void __launch_bounds__(128, 2)
mma_h(const __half* __restrict__ A, const __half* __restrict__ Bm,
      void* __restrict__ Cout,
      int K, int lda, int ldb, int ldc,
      long sAb, long sAh, long sBb, long sBh, long sCb, long sCh, int batchH,
      const float* __restrict__ bias, float scale, int flags)
{
    extern __shared__ __half hsm[];

    int bx, by;
    if (flags & F_SWAPXY) { bx = blockIdx.y; by = blockIdx.x; }
    else                  { bx = blockIdx.x; by = blockIdx.y; }
    if ((flags & F_CSKIP) && bx > by) return;

    int z  = blockIdx.z;
    int zb = z / batchH, zh = z % batchH;
    A  += zb * sAb + zh * sAh;
    Bm += zb * sBb + zh * sBh;
    long coff = zb * sCb + zh * sCh;

    int row0 = by * 128, col0 = bx * 128;

    int Keff = K;
    if (flags & F_CAUSALK) { int kl = (by + 1) * 128; if (kl < Keff) Keff = kl; }

    int tid  = threadIdx.x;
    int lane = tid & 31, warp = tid >> 5;
    int wm = warp >> 1, wn = warp & 1;
    int g  = lane >> 2, tig = lane & 3;

    const __half* Ag = A  + (size_t)row0 * lda;
    const __half* Bg = Bm + (size_t)col0 * ldb;

    unsigned sb = (unsigned)__cvta_generic_to_shared(hsm);

    float acc[4][8][4];
#pragma unroll
    for (int i = 0; i < 4; i++)
#pragma unroll
        for (int j = 0; j < 8; j++)
#pragma unroll
            for (int r = 0; r < 4; r++) acc[i][j][r] = 0.f;

    int iters = Keff / 32;

    // prologue: stages 0 and 1
#pragma unroll
    for (int st = 0; st < 2; st++) {
        if (st < iters) {
            __half* As = hsm + st * STG_H;
            __half* Bs = As + A_WH;
            int k0 = st * 32;
#pragma unroll
            for (int p = 0; p < 4; p++) {
                int c = p * 128 + tid;
                int row = c >> 2, ch = (c & 3) * 8;
                cp16(&As[(size_t)row * APH + ch], Ag + (size_t)row * lda + k0 + ch);
                cp16(&Bs[(size_t)row * APH + ch], Bg + (size_t)row * ldb + k0 + ch);
            }
            cp_commit();
        }
    }

    for (int it = 0; it < iters; ++it) {
        if (it + 1 < iters) asm volatile("cp.async.wait_group 1;\n" ::);
        else                asm volatile("cp.async.wait_group 0;\n" ::);
        __syncthreads();
        if (it + 2 < iters) {
            int st = (it + 2) % 3;
            int k0 = (it + 2) * 32;
            __half* As = hsm + st * STG_H;
            __half* Bs = As + A_WH;
#pragma unroll
            for (int p = 0; p < 4; p++) {
                int c = p * 128 + tid;
                int row = c >> 2, ch = (c & 3) * 8;
                cp16(&As[(size_t)row * APH + ch], Ag + (size_t)row * lda + k0 + ch);
                cp16(&Bs[(size_t)row * APH + ch], Bg + (size_t)row * ldb + k0 + ch);
            }
            cp_commit();
        }
        unsigned As_a = sb + (it % 3) * STG_BYTES;
        unsigned Bs_a = As_a + A_WH * 2;
        compute_k16(As_a, Bs_a, acc, 0,  wm, wn, lane);
        compute_k16(As_a, Bs_a, acc, 16, wm, wn, lane);
    }

    // epilogue
#pragma unroll
    for (int mt = 0; mt < 4; mt++) {
#pragma unroll
        for (int nt = 0; nt < 8; nt++) {
            int r = row0 + wm * 64 + mt * 16 + g;
            int c = col0 + wn * 64 + nt * 8 + tig * 2;
#pragma unroll
            for (int half_ = 0; half_ < 2; half_++) {
                int rr = r + 8 * half_;
                float x0 = acc[mt][nt][2*half_ + 0] * scale;
                float x1 = acc[mt][nt][2*half_ + 1] * scale;
                if (flags & F_BIAS) { x0 += bias[c]; x1 += bias[c + 1]; }
                if (flags & F_RELU) { x0 = fmaxf(x0, 0.f); x1 = fmaxf(x1, 0.f); }
                if (flags & F_OUTH) {
                    __half2 hv;
                    hv.x = __float2half_rn(x0);
                    hv.y = __float2half_rn(x1);
                    *(__half2*)((__half*)Cout + coff + (size_t)rr * ldc + c) = hv;
                } else {
                    float* p = (float*)Cout + coff + (size_t)rr * ldc + c;
                    if (flags & F_ADDC) { x0 += p[0]; x1 += p[1]; }
                    p[0] = x0; p[1] = x1;
                }
            }
        }
    }
}

// ---------------------------------------------------------------------------
// Host launch
// ---------------------------------------------------------------------------
extern "C" void kernel_launch(void* const* d_in, const int* in_sizes, int n_in,
                              void* d_out, int out_size) {
    const int*   idx = (const int*)  d_in[0];
    const float* tok = (const float*)d_in[1];
    const float* pos = (const float*)d_in[2];
    const float* Wq  = (const float*)d_in[3];
    const float* Wk  = (const float*)d_in[4];
    const float* Wv  = (const float*)d_in[5];
    const float* Wo  = (const float*)d_in[6];
    const float* bo  = (const float*)d_in[7];
    const float* W1  = (const float*)d_in[8];
    const float* b1  = (const float*)d_in[9];
    const float* W2  = (const float*)d_in[10];
    const float* b2  = (const float*)d_in[11];
    const float* g1  = (const float*)d_in[12];
    const float* be1 = (const float*)d_in[13];
    const float* g2  = (const float*)d_in[14];
    const float* be2 = (const float*)d_in[15];
    const float* gf  = (const float*)d_in[16];
    const float* bef = (const float*)d_in[17];
    const float* Wlm = (const float*)d_in[18];
    const float* blm = (const float*)d_in[19];
    float* out = (float*)d_out;

    float  *x, *wei;
    __half *hh, *qh, *kh, *vth, *ath, *fh, *ph;
    __half *WqT, *WkT, *WvT, *WoT, *W1T, *W2T, *WlmT;
    cudaGetSymbolAddress((void**)&x,    g_x);
    cudaGetSymbolAddress((void**)&wei,  g_wei);
    cudaGetSymbolAddress((void**)&hh,   g_hh);
    cudaGetSymbolAddress((void**)&qh,   g_qh);
    cudaGetSymbolAddress((void**)&kh,   g_kh);
    cudaGetSymbolAddress((void**)&vth,  g_vth);
    cudaGetSymbolAddress((void**)&ath,  g_ath);
    cudaGetSymbolAddress((void**)&fh,   g_fh);
    cudaGetSymbolAddress((void**)&ph,   g_ph);
    cudaGetSymbolAddress((void**)&WqT,  g_WqT);
    cudaGetSymbolAddress((void**)&WkT,  g_WkT);
    cudaGetSymbolAddress((void**)&WvT,  g_WvT);
    cudaGetSymbolAddress((void**)&WoT,  g_WoT);
    cudaGetSymbolAddress((void**)&W1T,  g_W1T);
    cudaGetSymbolAddress((void**)&W2T,  g_W2T);
    cudaGetSymbolAddress((void**)&WlmT, g_WlmT);

    cudaFuncSetAttribute(mma_h, cudaFuncAttributeMaxDynamicSharedMemorySize, SMEM_H);

    // 0. transpose + fp16-convert all weights (single fused launch)
    {
        TransArgs ta;
        ta.Wq = Wq; ta.Wk = Wk; ta.Wv = Wv; ta.Wo = Wo;
        ta.W1 = W1; ta.W2 = W2; ta.Wlm = Wlm;
        ta.cq = WqT; ta.ck = WkT; ta.cv = WvT; ta.co = WoT;
        ta.c1 = W1T; ta.c2 = W2T; ta.clm = WlmT;
        trans_all_kernel<<<T_TOT, dim3(32, 8)>>>(ta);
    }

    // 1. embedding
    embed_kernel<<<(B_*T_*C_)/256, 256>>>(idx, tok, pos);

    // 2. LN1 -> fp16
    ln_kernel<<<B_*T_, 256>>>(x, hh, g1, be1);

    // 3. q = h @ WqT^T, k likewise (fp16 out)
    {
        dim3 grid(D_/128, T_/128, B_*H_);
        mma_h<<<grid, 128, SMEM_H>>>(hh, WqT, qh, C_, C_, C_, D_,
            (long)T_*C_, 0, 0, (long)D_*C_, (long)H_*T_*D_, (long)T_*D_, H_,
            nullptr, 1.f, F_OUTH);
        mma_h<<<grid, 128, SMEM_H>>>(hh, WkT, kh, C_, C_, C_, D_,
            (long)T_*C_, 0, 0, (long)D_*C_, (long)H_*T_*D_, (long)T_*D_, H_,
            nullptr, 1.f, F_OUTH);
    }
    // 3b. vt[b,h,D,T] = WvT[D,C] @ h[T,C]^T (fp16 out)
    {
        dim3 grid(T_/128, D_/128, B_*H_);
        mma_h<<<grid, 128, SMEM_H>>>(WvT, hh, vth, C_, C_, C_, T_,
            0, (long)D_*C_, (long)T_*C_, 0, (long)H_*D_*T_, (long)D_*T_, H_,
            nullptr, 1.f, F_OUTH);
    }

    // 4. scores = q @ k^T * D^-0.5 (fp32 out, causal tile skip)
    {
        dim3 grid(T_/128, T_/128, B_*H_);
        mma_h<<<grid, 128, SMEM_H>>>(qh, kh, wei, D_, D_, D_, T_,
            (long)H_*T_*D_, (long)T_*D_, (long)H_*T_*D_, (long)T_*D_,
            (long)H_*T_*T_, (long)T_*T_, H_,
            nullptr, rsqrtf((float)D_), F_CSKIP);
    }

    // 5. softmax: fp32 scores -> fp16 probs (pad to 128)
    softmax_kernel<<<B_*H_*T_, 256>>>(wei, ph);

    // 6. att = probs @ vt^T -> [B,T,HD] fp16, causal K-limit
    {
        dim3 grid(D_/128, T_/128, B_*H_);
        mma_h<<<grid, 128, SMEM_H>>>(ph, vth, ath, T_, T_, T_, HD_,
            (long)H_*T_*T_, (long)T_*T_, (long)H_*D_*T_, (long)D_*T_,
            (long)T_*HD_, (long)D_, H_,
            nullptr, 1.f, F_CAUSALK | F_OUTH);
    }

    // 7. x += att @ WoT^T + bo (fp32)
    mma_h<<<dim3(C_/128, (B_*T_)/128, 1), 128, SMEM_H>>>(
        ath, WoT, x, HD_, HD_, HD_, C_,
        0, 0, 0, 0, 0, 0, 1, bo, 1.f, F_BIAS | F_ADDC);

    // 8. LN2 -> fp16
    ln_kernel<<<B_*T_, 256>>>(x, hh, g2, be2);

    // 9. ffn = relu(h @ W1T^T + b1) (fp16 out)
    mma_h<<<dim3(FF_/128, (B_*T_)/128, 1), 128, SMEM_H>>>(
        hh, W1T, fh, C_, C_, C_, FF_,
        0, 0, 0, 0, 0, 0, 1, b1, 1.f, F_BIAS | F_RELU | F_OUTH);

    // 10. x += ffn @ W2T^T + b2 (fp32)
    mma_h<<<dim3(C_/128, (B_*T_)/128, 1), 128, SMEM_H>>>(
        fh, W2T, x, FF_, FF_, FF_, C_,
        0, 0, 0, 0, 0, 0, 1, b2, 1.f, F_BIAS | F_ADDC);

    // 11. final LN -> fp16
    ln_kernel<<<B_*T_, 256>>>(x, hh, gf, bef);

    // 12. logits = h @ WlmT^T + blm (fp32 out, M-tiles on fast axis for L2 reuse)
    mma_h<<<dim3((B_*T_)/128, V_/128, 1), 128, SMEM_H>>>(
        hh, WlmT, out, C_, C_, C_, V_,
        0, 0, 0, 0, 0, 0, 1, blm, 1.f, F_BIAS | F_SWAPXY);
}

// round 16
// speedup vs baseline: 2.2896x; 1.1389x over previous
#include <cuda_runtime.h>
#include <cuda_fp16.h>
#include <math.h>

// Problem constants
#define B_ 2
#define T_ 2048
#define C_ 1024
#define H_ 8
#define D_ 1024
#define V_ 32000
#define HD_ (H_*D_)
#define FF_ (4*C_)

// fp32 buffers
__device__ float  g_x  [B_*T_*C_];                 // residual stream
__device__ float  g_wei[(size_t)B_*H_*T_*T_];      // raw scores (fp32 for softmax)
// fp16 operand buffers
__device__ __half g_hh [B_*T_*C_];                 // LN output
__device__ __half g_qh [B_*H_*T_*D_];
__device__ __half g_kh [B_*H_*T_*D_];
__device__ __half g_vth[B_*H_*D_*T_];              // v transposed [b,h,D,T]
__device__ __half g_ath[B_*T_*HD_];                // attention out
__device__ __half g_fh [B_*T_*FF_];                // ffn hidden
__device__ __half g_ph [(size_t)B_*H_*T_*T_];      // softmax probs
// transposed fp16 weights ([N,K] layouts)
__device__ __half g_WqT [H_*D_*C_];
__device__ __half g_WkT [H_*D_*C_];
__device__ __half g_WvT [H_*D_*C_];
__device__ __half g_WoT [C_*HD_];
__device__ __half g_W1T [FF_*C_];
__device__ __half g_W2T [C_*FF_];
__device__ __half g_WlmT[(size_t)V_*C_];

#define F_BIAS    1
#define F_ADDC    2
#define F_RELU    4
#define F_CAUSALK 8
#define F_OUTH    16
#define F_SWAPXY  32
#define F_CSKIP   64

// ---------------------------------------------------------------------------
// Fused transpose + fp16 convert for ALL weights: flat 1D grid, 32x32 tiles.
// ---------------------------------------------------------------------------
#define TQ_  8192
#define TWO_ 8192
#define TW1_ 4096
#define TW2_ 4096
#define TLM_ 32000
#define T_TOT (3*TQ_ + TWO_ + TW1_ + TW2_ + TLM_)

struct TransArgs {
    const float* Wq; const float* Wk; const float* Wv; const float* Wo;
    const float* W1; const float* W2; const float* Wlm;
    __half* cq; __half* ck; __half* cv; __half* co;
    __half* c1; __half* c2; __half* clm;
};

__global__ void trans_all_kernel(TransArgs args) {
    __shared__ float t[32][33];
    int tidx = blockIdx.x;
    const float* in; __half* out; int R, Cc;
    if (tidx < 3 * TQ_) {
        int w = tidx / TQ_, rem = tidx % TQ_;
        int hd = rem / 1024, tile = rem % 1024;
        const float* src = (w == 0) ? args.Wq : (w == 1) ? args.Wk : args.Wv;
        __half* dst = (w == 0) ? args.cq : (w == 1) ? args.ck : args.cv;
        in = src + (long)hd * C_ * D_;  out = dst + (long)hd * D_ * C_;
        R = C_; Cc = D_; tidx = tile;
    } else if (tidx < 3 * TQ_ + TWO_) {
        in = args.Wo; out = args.co; R = HD_; Cc = C_; tidx -= 3 * TQ_;
    } else if (tidx < 3 * TQ_ + TWO_ + TW1_) {
        in = args.W1; out = args.c1; R = C_; Cc = FF_; tidx -= 3 * TQ_ + TWO_;
    } else if (tidx < 3 * TQ_ + TWO_ + TW1_ + TW2_) {
        in = args.W2; out = args.c2; R = FF_; Cc = C_; tidx -= 3 * TQ_ + TWO_ + TW1_;
    } else {
        in = args.Wlm; out = args.clm; R = C_; Cc = V_; tidx -= 3 * TQ_ + TWO_ + TW1_ + TW2_;
    }
    int ntx = Cc / 32;
    int c0 = (tidx % ntx) * 32, r0 = (tidx / ntx) * 32;
    int x = threadIdx.x, y = threadIdx.y;   // 32 x 8
#pragma unroll
    for (int j = 0; j < 32; j += 8)
        t[y + j][x] = in[(size_t)(r0 + y + j) * Cc + c0 + x];
    __syncthreads();
#pragma unroll
    for (int j = 0; j < 32; j += 8)
        out[(size_t)(c0 + y + j) * R + r0 + x] = __float2half_rn(t[x][y + j]);
}

// ---------------------------------------------------------------------------
// Embedding (fp32 residual)
// ---------------------------------------------------------------------------
__global__ void embed_kernel(const int* __restrict__ idx,
                             const float* __restrict__ tok,
                             const float* __restrict__ pos) {
    int i = blockIdx.x * blockDim.x + threadIdx.x;
    int c  = i % C_;
    int bt = i / C_;
    int t  = bt % T_;
    g_x[i] = tok[(size_t)idx[bt] * C_ + c] + pos[t * C_ + c];
}

// ---------------------------------------------------------------------------
// LayerNorm: fp32 in -> fp16 out
// ---------------------------------------------------------------------------
__global__ void ln_kernel(const float* __restrict__ in, __half* __restrict__ out,
                          const float* __restrict__ g, const float* __restrict__ b) {
    int row = blockIdx.x;
    const float* x = in + (size_t)row * C_;
    __half* o = out + (size_t)row * C_;
    int tid = threadIdx.x;

    __shared__ float rs[256], rss[256];
    float s = 0.f, ss = 0.f;
    for (int c = tid; c < C_; c += 256) { float v = x[c]; s += v; ss += v * v; }
    rs[tid] = s; rss[tid] = ss;
    __syncthreads();
    for (int off = 128; off > 0; off >>= 1) {
        if (tid < off) { rs[tid] += rs[tid + off]; rss[tid] += rss[tid + off]; }
        __syncthreads();
    }
    float mean = rs[0] * (1.0f / C_);
    float var  = rss[0] * (1.0f / C_) - mean * mean;
    float inv  = rsqrtf(var + 1e-5f);
    for (int c = tid; c < C_; c += 256)
        o[c] = __float2half_rn((x[c] - mean) * inv * g[c] + b[c]);
}

// ---------------------------------------------------------------------------
// Causal softmax: fp32 scores -> fp16 probs; zero pad to next 128 boundary
// ---------------------------------------------------------------------------
__global__ void softmax_kernel(float* __restrict__ wei, __half* __restrict__ prob) {
    int row = blockIdx.x;
    int t = row % T_;
    float* w = wei + (size_t)row * T_;
    __half* ph = prob + (size_t)row * T_;
    int n = t + 1;
    int tid = threadIdx.x;
    __shared__ float red[256];

    float m = -1e30f;
    for (int s = tid; s < n; s += 256) m = fmaxf(m, w[s]);
    red[tid] = m;
    __syncthreads();
    for (int off = 128; off > 0; off >>= 1) {
        if (tid < off) red[tid] = fmaxf(red[tid], red[tid + off]);
        __syncthreads();
    }
    m = red[0];
    __syncthreads();

    float sum = 0.f;
    for (int s = tid; s < n; s += 256) { float e = expf(w[s] - m); w[s] = e; sum += e; }
    red[tid] = sum;
    __syncthreads();
    for (int off = 128; off > 0; off >>= 1) {
        if (tid < off) red[tid] += red[tid + off];
        __syncthreads();
    }
    float inv = 1.f / red[0];
    for (int s = tid; s < n; s += 256) ph[s] = __float2half_rn(w[s] * inv);

    int nend = (n + 127) & ~127;
    for (int s = n + tid; s < nend; s += 256) ph[s] = __float2half_rn(0.f);
}

// ---------------------------------------------------------------------------
// fp16 mma + ldmatrix helpers
// ---------------------------------------------------------------------------
__device__ __forceinline__ void mma16(float* d, const unsigned* a, unsigned b0, unsigned b1) {
    asm volatile(
        "mma.sync.aligned.m16n8k16.row.col.f32.f16.f16.f32 "
        "{%0,%1,%2,%3}, {%4,%5,%6,%7}, {%8,%9}, {%0,%1,%2,%3};\n"
        : "+f"(d[0]), "+f"(d[1]), "+f"(d[2]), "+f"(d[3])
        : "r"(a[0]), "r"(a[1]), "r"(a[2]), "r"(a[3]), "r"(b0), "r"(b1));
}

__device__ __forceinline__ void ldsm4(unsigned& r0, unsigned& r1, unsigned& r2, unsigned& r3,
                                      unsigned addr) {
    asm volatile("ldmatrix.sync.aligned.m8n8.x4.shared.b16 {%0,%1,%2,%3}, [%4];"
                 : "=r"(r0), "=r"(r1), "=r"(r2), "=r"(r3) : "r"(addr));
}

__device__ __forceinline__ void cp16(void* s, const void* g) {
    unsigned sa = (unsigned)__cvta_generic_to_shared(s);
    asm volatile("cp.async.cg.shared.global [%0], [%1], 16;\n" :: "r"(sa), "l"(g));
}
__device__ __forceinline__ void cp_commit() {
    asm volatile("cp.async.commit_group;\n" ::);
}

// Tiles: [128 rows][K=32 halves, stride 40 halves = 80 B]
#define APH 40
#define A_WH (128*APH)          // halves per operand stage (5120)
#define STG_H (2*A_WH)          // halves per stage
#define STG_BYTES (STG_H*2)     // 20480
#define SMEM_H (3*STG_BYTES)    // 61440

// Warp tile 64x64: 4 m-subtiles x 8 n-subtiles; fragments via ldmatrix.x4
__device__ __forceinline__ void compute_k16(
    unsigned As, unsigned Bs, float acc[4][8][4],
    int kk, int wm, int wn, int lane)
{
    unsigned aoff = As + (((lane & 15) * APH + ((lane >> 4) << 3) + kk) << 1);
    unsigned a[4][4];
#pragma unroll
    for (int mt = 0; mt < 4; mt++)
        ldsm4(a[mt][0], a[mt][1], a[mt][2], a[mt][3],
              aoff + ((wm * 64 + mt * 16) * APH << 1));

    unsigned boff = Bs + ((((lane & 7) + ((lane & 16) >> 1)) * APH
                           + ((lane & 8) ? 8 : 0) + kk) << 1);
#pragma unroll
    for (int ntp = 0; ntp < 4; ntp++) {
        unsigned b0, b1, b2, b3;
        ldsm4(b0, b1, b2, b3, boff + ((wn * 64 + ntp * 16) * APH << 1));
#pragma unroll
        for (int mt = 0; mt < 4; mt++) mma16(acc[mt][2 * ntp    ], a[mt], b0, b1);
#pragma unroll
        for (int mt = 0; mt < 4; mt++) mma16(acc[mt][2 * ntp + 1], a[mt], b2, b3);
    }
}

// ---------------------------------------------------------------------------
// Unified fp16 NT GEMM: C[M,N] (+)= scale * A[M,K] @ B[N,K]^T
// 128x128 tile, BK=32, 128 threads, 3-stage ring, 1 sync/iter, 3 CTAs/SM
// ---------------------------------------------------------------------------
__global__ void __launch_bounds__(128, 3)
mma_h(const __half* __restrict__ A, const __half* __restrict__ Bm,
      void* __restrict__ Cout,
      int K, int lda, int ldb, int ldc,
      long sAb, long sAh, long sBb, long sBh, long sCb, long sCh, int batchH,
      const float* __restrict__ bias, float scale, int flags)
{
    extern __shared__ __half hsm[];

    int bx, by;
    if (flags & F_SWAPXY) { bx = blockIdx.y; by = blockIdx.x; }
    else                  { bx = blockIdx.x; by = blockIdx.y; }
    if ((flags & F_CSKIP) && bx > by) return;

    int z  = blockIdx.z;
    int zb = z / batchH, zh = z % batchH;
    A  += zb * sAb + zh * sAh;
    Bm += zb * sBb + zh * sBh;
    long coff = zb * sCb + zh * sCh;

    int row0 = by * 128, col0 = bx * 128;

    int Keff = K;
    if (flags & F_CAUSALK) { int kl = (by + 1) * 128; if (kl < Keff) Keff = kl; }

    int tid  = threadIdx.x;
    int lane = tid & 31, warp = tid >> 5;
    int wm = warp >> 1, wn = warp & 1;
    int g  = lane >> 2, tig = lane & 3;

    const __half* Ag = A  + (size_t)row0 * lda;
    const __half* Bg = Bm + (size_t)col0 * ldb;

    unsigned sb = (unsigned)__cvta_generic_to_shared(hsm);

    float acc[4][8][4];
#pragma unroll
    for (int i = 0; i < 4; i++)
#pragma unroll
        for (int j = 0; j < 8; j++)
#pragma unroll
            for (int r = 0; r < 4; r++) acc[i][j][r] = 0.f;

    int iters = Keff / 32;

    // prologue: stages 0 and 1
#pragma unroll
    for (int st = 0; st < 2; st++) {
        if (st < iters) {
            __half* As = hsm + st * STG_H;
            __half* Bs = As + A_WH;
            int k0 = st * 32;
#pragma unroll
            for (int p = 0; p < 4; p++) {
                int c = p * 128 + tid;
                int row = c >> 2, ch = (c & 3) * 8;
                cp16(&As[(size_t)row * APH + ch], Ag + (size_t)row * lda + k0 + ch);
                cp16(&Bs[(size_t)row * APH + ch], Bg + (size_t)row * ldb + k0 + ch);
            }
            cp_commit();
        }
    }

    for (int it = 0; it < iters; ++it) {
        if (it + 1 < iters) asm volatile("cp.async.wait_group 1;\n" ::);
        else                asm volatile("cp.async.wait_group 0;\n" ::);
        __syncthreads();
        if (it + 2 < iters) {
            int st = (it + 2) % 3;
            int k0 = (it + 2) * 32;
            __half* As = hsm + st * STG_H;
            __half* Bs = As + A_WH;
#pragma unroll
            for (int p = 0; p < 4; p++) {
                int c = p * 128 + tid;
                int row = c >> 2, ch = (c & 3) * 8;
                cp16(&As[(size_t)row * APH + ch], Ag + (size_t)row * lda + k0 + ch);
                cp16(&Bs[(size_t)row * APH + ch], Bg + (size_t)row * ldb + k0 + ch);
            }
            cp_commit();
        }
        unsigned As_a = sb + (it % 3) * STG_BYTES;
        unsigned Bs_a = As_a + A_WH * 2;
        compute_k16(As_a, Bs_a, acc, 0,  wm, wn, lane);
        compute_k16(As_a, Bs_a, acc, 16, wm, wn, lane);
    }

    // epilogue
#pragma unroll
    for (int mt = 0; mt < 4; mt++) {
#pragma unroll
        for (int nt = 0; nt < 8; nt++) {
            int r = row0 + wm * 64 + mt * 16 + g;
            int c = col0 + wn * 64 + nt * 8 + tig * 2;
#pragma unroll
            for (int half_ = 0; half_ < 2; half_++) {
                int rr = r + 8 * half_;
                float x0 = acc[mt][nt][2*half_ + 0] * scale;
                float x1 = acc[mt][nt][2*half_ + 1] * scale;
                if (flags & F_BIAS) { x0 += bias[c]; x1 += bias[c + 1]; }
                if (flags & F_RELU) { x0 = fmaxf(x0, 0.f); x1 = fmaxf(x1, 0.f); }
                if (flags & F_OUTH) {
                    __half2 hv;
                    hv.x = __float2half_rn(x0);
                    hv.y = __float2half_rn(x1);
                    *(__half2*)((__half*)Cout + coff + (size_t)rr * ldc + c) = hv;
                } else {
                    float* p = (float*)Cout + coff + (size_t)rr * ldc + c;
                    if (flags & F_ADDC) { x0 += p[0]; x1 += p[1]; }
                    p[0] = x0; p[1] = x1;
                }
            }
        }
    }
}

// ---------------------------------------------------------------------------
// Host launch
// ---------------------------------------------------------------------------
extern "C" void kernel_launch(void* const* d_in, const int* in_sizes, int n_in,
                              void* d_out, int out_size) {
    const int*   idx = (const int*)  d_in[0];
    const float* tok = (const float*)d_in[1];
    const float* pos = (const float*)d_in[2];
    const float* Wq  = (const float*)d_in[3];
    const float* Wk  = (const float*)d_in[4];
    const float* Wv  = (const float*)d_in[5];
    const float* Wo  = (const float*)d_in[6];
    const float* bo  = (const float*)d_in[7];
    const float* W1  = (const float*)d_in[8];
    const float* b1  = (const float*)d_in[9];
    const float* W2  = (const float*)d_in[10];
    const float* b2  = (const float*)d_in[11];
    const float* g1  = (const float*)d_in[12];
    const float* be1 = (const float*)d_in[13];
    const float* g2  = (const float*)d_in[14];
    const float* be2 = (const float*)d_in[15];
    const float* gf  = (const float*)d_in[16];
    const float* bef = (const float*)d_in[17];
    const float* Wlm = (const float*)d_in[18];
    const float* blm = (const float*)d_in[19];
    float* out = (float*)d_out;

    float  *x, *wei;
    __half *hh, *qh, *kh, *vth, *ath, *fh, *ph;
    __half *WqT, *WkT, *WvT, *WoT, *W1T, *W2T, *WlmT;
    cudaGetSymbolAddress((void**)&x,    g_x);
    cudaGetSymbolAddress((void**)&wei,  g_wei);
    cudaGetSymbolAddress((void**)&hh,   g_hh);
    cudaGetSymbolAddress((void**)&qh,   g_qh);
    cudaGetSymbolAddress((void**)&kh,   g_kh);
    cudaGetSymbolAddress((void**)&vth,  g_vth);
    cudaGetSymbolAddress((void**)&ath,  g_ath);
    cudaGetSymbolAddress((void**)&fh,   g_fh);
    cudaGetSymbolAddress((void**)&ph,   g_ph);
    cudaGetSymbolAddress((void**)&WqT,  g_WqT);
    cudaGetSymbolAddress((void**)&WkT,  g_WkT);
    cudaGetSymbolAddress((void**)&WvT,  g_WvT);
    cudaGetSymbolAddress((void**)&WoT,  g_WoT);
    cudaGetSymbolAddress((void**)&W1T,  g_W1T);
    cudaGetSymbolAddress((void**)&W2T,  g_W2T);
    cudaGetSymbolAddress((void**)&WlmT, g_WlmT);

    cudaFuncSetAttribute(mma_h, cudaFuncAttributeMaxDynamicSharedMemorySize, SMEM_H);

    // 0. transpose + fp16-convert all weights (single fused launch)
    {
        TransArgs ta;
        ta.Wq = Wq; ta.Wk = Wk; ta.Wv = Wv; ta.Wo = Wo;
        ta.W1 = W1; ta.W2 = W2; ta.Wlm = Wlm;
        ta.cq = WqT; ta.ck = WkT; ta.cv = WvT; ta.co = WoT;
        ta.c1 = W1T; ta.c2 = W2T; ta.clm = WlmT;
        trans_all_kernel<<<T_TOT, dim3(32, 8)>>>(ta);
    }

    // 1. embedding
    embed_kernel<<<(B_*T_*C_)/256, 256>>>(idx, tok, pos);

    // 2. LN1 -> fp16
    ln_kernel<<<B_*T_, 256>>>(x, hh, g1, be1);

    // 3. q = h @ WqT^T, k likewise (fp16 out)
    {
        dim3 grid(D_/128, T_/128, B_*H_);
        mma_h<<<grid, 128, SMEM_H>>>(hh, WqT, qh, C_, C_, C_, D_,
            (long)T_*C_, 0, 0, (long)D_*C_, (long)H_*T_*D_, (long)T_*D_, H_,
            nullptr, 1.f, F_OUTH);
        mma_h<<<grid, 128, SMEM_H>>>(hh, WkT, kh, C_, C_, C_, D_,
            (long)T_*C_, 0, 0, (long)D_*C_, (long)H_*T_*D_, (long)T_*D_, H_,
            nullptr, 1.f, F_OUTH);
    }
    // 3b. vt[b,h,D,T] = WvT[D,C] @ h[T,C]^T (fp16 out)
    {
        dim3 grid(T_/128, D_/128, B_*H_);
        mma_h<<<grid, 128, SMEM_H>>>(WvT, hh, vth, C_, C_, C_, T_,
            0, (long)D_*C_, (long)T_*C_, 0, (long)H_*D_*T_, (long)D_*T_, H_,
            nullptr, 1.f, F_OUTH);
    }

    // 4. scores = q @ k^T * D^-0.5 (fp32 out, causal tile skip)
    {
        dim3 grid(T_/128, T_/128, B_*H_);
        mma_h<<<grid, 128, SMEM_H>>>(qh, kh, wei, D_, D_, D_, T_,
            (long)H_*T_*D_, (long)T_*D_, (long)H_*T_*D_, (long)T_*D_,
            (long)H_*T_*T_, (long)T_*T_, H_,
            nullptr, rsqrtf((float)D_), F_CSKIP);
    }

    // 5. softmax: fp32 scores -> fp16 probs (pad to 128)
    softmax_kernel<<<B_*H_*T_, 256>>>(wei, ph);

    // 6. att = probs @ vt^T -> [B,T,HD] fp16, causal K-limit
    {
        dim3 grid(D_/128, T_/128, B_*H_);
        mma_h<<<grid, 128, SMEM_H>>>(ph, vth, ath, T_, T_, T_, HD_,
            (long)H_*T_*T_, (long)T_*T_, (long)H_*D_*T_, (long)D_*T_,
            (long)T_*HD_, (long)D_, H_,
            nullptr, 1.f, F_CAUSALK | F_OUTH);
    }

    // 7. x += att @ WoT^T + bo (fp32)
    mma_h<<<dim3(C_/128, (B_*T_)/128, 1), 128, SMEM_H>>>(
        ath, WoT, x, HD_, HD_, HD_, C_,
        0, 0, 0, 0, 0, 0, 1, bo, 1.f, F_BIAS | F_ADDC);

    // 8. LN2 -> fp16
    ln_kernel<<<B_*T_, 256>>>(x, hh, g2, be2);

    // 9. ffn = relu(h @ W1T^T + b1) (fp16 out)
    mma_h<<<dim3(FF_/128, (B_*T_)/128, 1), 128, SMEM_H>>>(
        hh, W1T, fh, C_, C_, C_, FF_,
        0, 0, 0, 0, 0, 0, 1, b1, 1.f, F_BIAS | F_RELU | F_OUTH);

    // 10. x += ffn @ W2T^T + b2 (fp32)
    mma_h<<<dim3(C_/128, (B_*T_)/128, 1), 128, SMEM_H>>>(
        fh, W2T, x, FF_, FF_, FF_, C_,
        0, 0, 0, 0, 0, 0, 1, b2, 1.f, F_BIAS | F_ADDC);

    // 11. final LN -> fp16
    ln_kernel<<<B_*T_, 256>>>(x, hh, gf, bef);

    // 12. logits = h @ WlmT^T + blm (fp32 out, M-tiles on fast axis for L2 reuse)
    mma_h<<<dim3((B_*T_)/128, V_/128, 1), 128, SMEM_H>>>(
        hh, WlmT, out, C_, C_, C_, V_,
        0, 0, 0, 0, 0, 0, 1, blm, 1.f, F_BIAS | F_SWAPXY);
}

// round 17
// speedup vs baseline: 2.3176x; 1.0123x over previous
#include <cuda_runtime.h>
#include <cuda_fp16.h>
#include <math.h>

// Problem constants
#define B_ 2
#define T_ 2048
#define C_ 1024
#define H_ 8
#define D_ 1024
#define V_ 32000
#define HD_ (H_*D_)
#define FF_ (4*C_)

// fp32 buffers
__device__ float  g_x  [B_*T_*C_];                 // residual stream
__device__ float  g_wei[(size_t)B_*H_*T_*T_];      // raw scores (fp32 for softmax)
// fp16 operand buffers
__device__ __half g_hh [B_*T_*C_];                 // LN output
__device__ __half g_qh [B_*H_*T_*D_];
__device__ __half g_kh [B_*H_*T_*D_];
__device__ __half g_vth[B_*H_*D_*T_];              // v transposed [b,h,D,T]
__device__ __half g_ath[B_*T_*HD_];                // attention out
__device__ __half g_fh [B_*T_*FF_];                // ffn hidden
__device__ __half g_ph [(size_t)B_*H_*T_*T_];      // softmax probs
// transposed fp16 weights ([N,K] layouts)
__device__ __half g_WqT [H_*D_*C_];
__device__ __half g_WkT [H_*D_*C_];
__device__ __half g_WvT [H_*D_*C_];
__device__ __half g_WoT [C_*HD_];
__device__ __half g_W1T [FF_*C_];
__device__ __half g_W2T [C_*FF_];
__device__ __half g_WlmT[(size_t)V_*C_];

#define F_BIAS    1
#define F_ADDC    2
#define F_RELU    4
#define F_CAUSALK 8
#define F_OUTH    16
#define F_SWAPXY  32
#define F_CSKIP   64

// ---------------------------------------------------------------------------
// Fused transpose + fp16 convert for ALL weights: flat 1D grid, 32x32 tiles.
// ---------------------------------------------------------------------------
#define TQ_  8192
#define TWO_ 8192
#define TW1_ 4096
#define TW2_ 4096
#define TLM_ 32000
#define T_TOT (3*TQ_ + TWO_ + TW1_ + TW2_ + TLM_)

struct TransArgs {
    const float* Wq; const float* Wk; const float* Wv; const float* Wo;
    const float* W1; const float* W2; const float* Wlm;
    __half* cq; __half* ck; __half* cv; __half* co;
    __half* c1; __half* c2; __half* clm;
};

__global__ void trans_all_kernel(TransArgs args) {
    __shared__ float t[32][33];
    int tidx = blockIdx.x;
    const float* in; __half* out; int R, Cc;
    if (tidx < 3 * TQ_) {
        int w = tidx / TQ_, rem = tidx % TQ_;
        int hd = rem / 1024, tile = rem % 1024;
        const float* src = (w == 0) ? args.Wq : (w == 1) ? args.Wk : args.Wv;
        __half* dst = (w == 0) ? args.cq : (w == 1) ? args.ck : args.cv;
        in = src + (long)hd * C_ * D_;  out = dst + (long)hd * D_ * C_;
        R = C_; Cc = D_; tidx = tile;
    } else if (tidx < 3 * TQ_ + TWO_) {
        in = args.Wo; out = args.co; R = HD_; Cc = C_; tidx -= 3 * TQ_;
    } else if (tidx < 3 * TQ_ + TWO_ + TW1_) {
        in = args.W1; out = args.c1; R = C_; Cc = FF_; tidx -= 3 * TQ_ + TWO_;
    } else if (tidx < 3 * TQ_ + TWO_ + TW1_ + TW2_) {
        in = args.W2; out = args.c2; R = FF_; Cc = C_; tidx -= 3 * TQ_ + TWO_ + TW1_;
    } else {
        in = args.Wlm; out = args.clm; R = C_; Cc = V_; tidx -= 3 * TQ_ + TWO_ + TW1_ + TW2_;
    }
    int ntx = Cc / 32;
    int c0 = (tidx % ntx) * 32, r0 = (tidx / ntx) * 32;
    int x = threadIdx.x, y = threadIdx.y;   // 32 x 8
#pragma unroll
    for (int j = 0; j < 32; j += 8)
        t[y + j][x] = in[(size_t)(r0 + y + j) * Cc + c0 + x];
    __syncthreads();
#pragma unroll
    for (int j = 0; j < 32; j += 8)
        out[(size_t)(c0 + y + j) * R + r0 + x] = __float2half_rn(t[x][y + j]);
}

// ---------------------------------------------------------------------------
// Embedding (fp32 residual)
// ---------------------------------------------------------------------------
__global__ void embed_kernel(const int* __restrict__ idx,
                             const float* __restrict__ tok,
                             const float* __restrict__ pos) {
    int i = blockIdx.x * blockDim.x + threadIdx.x;
    int c  = i % C_;
    int bt = i / C_;
    int t  = bt % T_;
    g_x[i] = tok[(size_t)idx[bt] * C_ + c] + pos[t * C_ + c];
}

// ---------------------------------------------------------------------------
// LayerNorm: fp32 in -> fp16 out
// ---------------------------------------------------------------------------
__global__ void ln_kernel(const float* __restrict__ in, __half* __restrict__ out,
                          const float* __restrict__ g, const float* __restrict__ b) {
    int row = blockIdx.x;
    const float* x = in + (size_t)row * C_;
    __half* o = out + (size_t)row * C_;
    int tid = threadIdx.x;

    __shared__ float rs[256], rss[256];
    float s = 0.f, ss = 0.f;
    for (int c = tid; c < C_; c += 256) { float v = x[c]; s += v; ss += v * v; }
    rs[tid] = s; rss[tid] = ss;
    __syncthreads();
    for (int off = 128; off > 0; off >>= 1) {
        if (tid < off) { rs[tid] += rs[tid + off]; rss[tid] += rss[tid + off]; }
        __syncthreads();
    }
    float mean = rs[0] * (1.0f / C_);
    float var  = rss[0] * (1.0f / C_) - mean * mean;
    float inv  = rsqrtf(var + 1e-5f);
    for (int c = tid; c < C_; c += 256)
        o[c] = __float2half_rn((x[c] - mean) * inv * g[c] + b[c]);
}

// ---------------------------------------------------------------------------
// Causal softmax: fp32 scores -> fp16 probs; zero pad to next 128 boundary
// ---------------------------------------------------------------------------
__global__ void softmax_kernel(float* __restrict__ wei, __half* __restrict__ prob) {
    int row = blockIdx.x;
    int t = row % T_;
    float* w = wei + (size_t)row * T_;
    __half* ph = prob + (size_t)row * T_;
    int n = t + 1;
    int tid = threadIdx.x;
    __shared__ float red[256];

    float m = -1e30f;
    for (int s = tid; s < n; s += 256) m = fmaxf(m, w[s]);
    red[tid] = m;
    __syncthreads();
    for (int off = 128; off > 0; off >>= 1) {
        if (tid < off) red[tid] = fmaxf(red[tid], red[tid + off]);
        __syncthreads();
    }
    m = red[0];
    __syncthreads();

    float sum = 0.f;
    for (int s = tid; s < n; s += 256) { float e = expf(w[s] - m); w[s] = e; sum += e; }
    red[tid] = sum;
    __syncthreads();
    for (int off = 128; off > 0; off >>= 1) {
        if (tid < off) red[tid] += red[tid + off];
        __syncthreads();
    }
    float inv = 1.f / red[0];
    for (int s = tid; s < n; s += 256) ph[s] = __float2half_rn(w[s] * inv);

    int nend = (n + 127) & ~127;
    for (int s = n + tid; s < nend; s += 256) ph[s] = __float2half_rn(0.f);
}

// ---------------------------------------------------------------------------
// fp16 mma + ldmatrix helpers
// ---------------------------------------------------------------------------
__device__ __forceinline__ void mma16(float* d, const unsigned* a, unsigned b0, unsigned b1) {
    asm volatile(
        "mma.sync.aligned.m16n8k16.row.col.f32.f16.f16.f32 "
        "{%0,%1,%2,%3}, {%4,%5,%6,%7}, {%8,%9}, {%0,%1,%2,%3};\n"
        : "+f"(d[0]), "+f"(d[1]), "+f"(d[2]), "+f"(d[3])
        : "r"(a[0]), "r"(a[1]), "r"(a[2]), "r"(a[3]), "r"(b0), "r"(b1));
}

__device__ __forceinline__ void ldsm4(unsigned& r0, unsigned& r1, unsigned& r2, unsigned& r3,
                                      unsigned addr) {
    asm volatile("ldmatrix.sync.aligned.m8n8.x4.shared.b16 {%0,%1,%2,%3}, [%4];"
                 : "=r"(r0), "=r"(r1), "=r"(r2), "=r"(r3) : "r"(addr));
}

__device__ __forceinline__ void cp16(void* s, const void* g) {
    unsigned sa = (unsigned)__cvta_generic_to_shared(s);
    asm volatile("cp.async.cg.shared.global [%0], [%1], 16;\n" :: "r"(sa), "l"(g));
}
__device__ __forceinline__ void cp_commit() {
    asm volatile("cp.async.commit_group;\n" ::);
}

// Tiles: [128 rows][K=32 halves, stride 40 halves = 80 B]
#define APH 40
#define A_WH (128*APH)          // halves per operand stage (5120)
#define STG_H (2*A_WH)          // halves per stage
#define STG_BYTES (STG_H*2)     // 20480
#define SMEM_H (3*STG_BYTES)    // 61440

// Warp tile 64x32: 4 m-subtiles x 4 n-subtiles; fragments via ldmatrix.x4
__device__ __forceinline__ void compute_k16(
    unsigned As, unsigned Bs, float acc[4][4][4],
    int kk, int wm, int wn, int lane)
{
    unsigned aoff = As + (((lane & 15) * APH + ((lane >> 4) << 3) + kk) << 1);
    unsigned a[4][4];
#pragma unroll
    for (int mt = 0; mt < 4; mt++)
        ldsm4(a[mt][0], a[mt][1], a[mt][2], a[mt][3],
              aoff + ((wm * 64 + mt * 16) * APH << 1));

    unsigned boff = Bs + ((((lane & 7) + ((lane & 16) >> 1)) * APH
                           + ((lane & 8) ? 8 : 0) + kk) << 1);
#pragma unroll
    for (int ntp = 0; ntp < 2; ntp++) {
        unsigned b0, b1, b2, b3;
        ldsm4(b0, b1, b2, b3, boff + ((wn * 32 + ntp * 16) * APH << 1));
#pragma unroll
        for (int mt = 0; mt < 4; mt++) mma16(acc[mt][2 * ntp    ], a[mt], b0, b1);
#pragma unroll
        for (int mt = 0; mt < 4; mt++) mma16(acc[mt][2 * ntp + 1], a[mt], b2, b3);
    }
}

// ---------------------------------------------------------------------------
// Unified fp16 NT GEMM: C[M,N] (+)= scale * A[M,K] @ B[N,K]^T
// 128x128 tile, BK=32, 256 threads (8 warps of 64x32, 2m x 4n),
// 3-stage ring, 1 sync/iter, 2 CTAs/SM => 16 warps/SM
// ---------------------------------------------------------------------------
__global__ void __launch_bounds__(256, 2)
mma_h(const __half* __restrict__ A, const __half* __restrict__ Bm,
      void* __restrict__ Cout,
      int K, int lda, int ldb, int ldc,
      long sAb, long sAh, long sBb, long sBh, long sCb, long sCh, int batchH,
      const float* __restrict__ bias, float scale, int flags)
{
    extern __shared__ __half hsm[];

    int bx, by;
    if (flags & F_SWAPXY) { bx = blockIdx.y; by = blockIdx.x; }
    else                  { bx = blockIdx.x; by = blockIdx.y; }
    if ((flags & F_CSKIP) && bx > by) return;

    int z  = blockIdx.z;
    int zb = z / batchH, zh = z % batchH;
    A  += zb * sAb + zh * sAh;
    Bm += zb * sBb + zh * sBh;
    long coff = zb * sCb + zh * sCh;

    int row0 = by * 128, col0 = bx * 128;

    int Keff = K;
    if (flags & F_CAUSALK) { int kl = (by + 1) * 128; if (kl < Keff) Keff = kl; }

    int tid  = threadIdx.x;
    int lane = tid & 31, warp = tid >> 5;
    int wm = warp >> 2, wn = warp & 3;      // 2m x 4n warp grid
    int g  = lane >> 2, tig = lane & 3;

    const __half* Ag = A  + (size_t)row0 * lda;
    const __half* Bg = Bm + (size_t)col0 * ldb;

    unsigned sb = (unsigned)__cvta_generic_to_shared(hsm);

    float acc[4][4][4];
#pragma unroll
    for (int i = 0; i < 4; i++)
#pragma unroll
        for (int j = 0; j < 4; j++)
#pragma unroll
            for (int r = 0; r < 4; r++) acc[i][j][r] = 0.f;

    int iters = Keff / 32;

    // prologue: stages 0 and 1 (256 threads: 2 chunks per operand per thread)
#pragma unroll
    for (int st = 0; st < 2; st++) {
        if (st < iters) {
            __half* As = hsm + st * STG_H;
            __half* Bs = As + A_WH;
            int k0 = st * 32;
#pragma unroll
            for (int p = 0; p < 2; p++) {
                int c = p * 256 + tid;
                int row = c >> 2, ch = (c & 3) * 8;
                cp16(&As[(size_t)row * APH + ch], Ag + (size_t)row * lda + k0 + ch);
                cp16(&Bs[(size_t)row * APH + ch], Bg + (size_t)row * ldb + k0 + ch);
            }
            cp_commit();
        }
    }

    for (int it = 0; it < iters; ++it) {
        if (it + 1 < iters) asm volatile("cp.async.wait_group 1;\n" ::);
        else                asm volatile("cp.async.wait_group 0;\n" ::);
        __syncthreads();
        unsigned As_a = sb + (it % 3) * STG_BYTES;
        unsigned Bs_a = As_a + A_WH * 2;
        compute_k16(As_a, Bs_a, acc, 0, wm, wn, lane);
        if (it + 2 < iters) {
            int st = (it + 2) % 3;
            int k0 = (it + 2) * 32;
            __half* As = hsm + st * STG_H;
            __half* Bs = As + A_WH;
#pragma unroll
            for (int p = 0; p < 2; p++) {
                int c = p * 256 + tid;
                int row = c >> 2, ch = (c & 3) * 8;
                cp16(&As[(size_t)row * APH + ch], Ag + (size_t)row * lda + k0 + ch);
                cp16(&Bs[(size_t)row * APH + ch], Bg + (size_t)row * ldb + k0 + ch);
            }
            cp_commit();
        }
        compute_k16(As_a, Bs_a, acc, 16, wm, wn, lane);
    }

    // epilogue
#pragma unroll
    for (int mt = 0; mt < 4; mt++) {
#pragma unroll
        for (int nt = 0; nt < 4; nt++) {
            int r = row0 + wm * 64 + mt * 16 + g;
            int c = col0 + wn * 32 + nt * 8 + tig * 2;
#pragma unroll
            for (int half_ = 0; half_ < 2; half_++) {
                int rr = r + 8 * half_;
                float x0 = acc[mt][nt][2*half_ + 0] * scale;
                float x1 = acc[mt][nt][2*half_ + 1] * scale;
                if (flags & F_BIAS) { x0 += bias[c]; x1 += bias[c + 1]; }
                if (flags & F_RELU) { x0 = fmaxf(x0, 0.f); x1 = fmaxf(x1, 0.f); }
                if (flags & F_OUTH) {
                    __half2 hv;
                    hv.x = __float2half_rn(x0);
                    hv.y = __float2half_rn(x1);
                    *(__half2*)((__half*)Cout + coff + (size_t)rr * ldc + c) = hv;
                } else {
                    float* p = (float*)Cout + coff + (size_t)rr * ldc + c;
                    if (flags & F_ADDC) { x0 += p[0]; x1 += p[1]; }
                    p[0] = x0; p[1] = x1;
                }
            }
        }
    }
}

// ---------------------------------------------------------------------------
// Host launch
// ---------------------------------------------------------------------------
extern "C" void kernel_launch(void* const* d_in, const int* in_sizes, int n_in,
                              void* d_out, int out_size) {
    const int*   idx = (const int*)  d_in[0];
    const float* tok = (const float*)d_in[1];
    const float* pos = (const float*)d_in[2];
    const float* Wq  = (const float*)d_in[3];
    const float* Wk  = (const float*)d_in[4];
    const float* Wv  = (const float*)d_in[5];
    const float* Wo  = (const float*)d_in[6];
    const float* bo  = (const float*)d_in[7];
    const float* W1  = (const float*)d_in[8];
    const float* b1  = (const float*)d_in[9];
    const float* W2  = (const float*)d_in[10];
    const float* b2  = (const float*)d_in[11];
    const float* g1  = (const float*)d_in[12];
    const float* be1 = (const float*)d_in[13];
    const float* g2  = (const float*)d_in[14];
    const float* be2 = (const float*)d_in[15];
    const float* gf  = (const float*)d_in[16];
    const float* bef = (const float*)d_in[17];
    const float* Wlm = (const float*)d_in[18];
    const float* blm = (const float*)d_in[19];
    float* out = (float*)d_out;

    float  *x, *wei;
    __half *hh, *qh, *kh, *vth, *ath, *fh, *ph;
    __half *WqT, *WkT, *WvT, *WoT, *W1T, *W2T, *WlmT;
    cudaGetSymbolAddress((void**)&x,    g_x);
    cudaGetSymbolAddress((void**)&wei,  g_wei);
    cudaGetSymbolAddress((void**)&hh,   g_hh);
    cudaGetSymbolAddress((void**)&qh,   g_qh);
    cudaGetSymbolAddress((void**)&kh,   g_kh);
    cudaGetSymbolAddress((void**)&vth,  g_vth);
    cudaGetSymbolAddress((void**)&ath,  g_ath);
    cudaGetSymbolAddress((void**)&fh,   g_fh);
    cudaGetSymbolAddress((void**)&ph,   g_ph);
    cudaGetSymbolAddress((void**)&WqT,  g_WqT);
    cudaGetSymbolAddress((void**)&WkT,  g_WkT);
    cudaGetSymbolAddress((void**)&WvT,  g_WvT);
    cudaGetSymbolAddress((void**)&WoT,  g_WoT);
    cudaGetSymbolAddress((void**)&W1T,  g_W1T);
    cudaGetSymbolAddress((void**)&W2T,  g_W2T);
    cudaGetSymbolAddress((void**)&WlmT, g_WlmT);

    cudaFuncSetAttribute(mma_h, cudaFuncAttributeMaxDynamicSharedMemorySize, SMEM_H);

    // 0. transpose + fp16-convert all weights (single fused launch)
    {
        TransArgs ta;
        ta.Wq = Wq; ta.Wk = Wk; ta.Wv = Wv; ta.Wo = Wo;
        ta.W1 = W1; ta.W2 = W2; ta.Wlm = Wlm;
        ta.cq = WqT; ta.ck = WkT; ta.cv = WvT; ta.co = WoT;
        ta.c1 = W1T; ta.c2 = W2T; ta.clm = WlmT;
        trans_all_kernel<<<T_TOT, dim3(32, 8)>>>(ta);
    }

    // 1. embedding
    embed_kernel<<<(B_*T_*C_)/256, 256>>>(idx, tok, pos);

    // 2. LN1 -> fp16
    ln_kernel<<<B_*T_, 256>>>(x, hh, g1, be1);

    // 3. q = h @ WqT^T, k likewise (fp16 out)
    {
        dim3 grid(D_/128, T_/128, B_*H_);
        mma_h<<<grid, 256, SMEM_H>>>(hh, WqT, qh, C_, C_, C_, D_,
            (long)T_*C_, 0, 0, (long)D_*C_, (long)H_*T_*D_, (long)T_*D_, H_,
            nullptr, 1.f, F_OUTH);
        mma_h<<<grid, 256, SMEM_H>>>(hh, WkT, kh, C_, C_, C_, D_,
            (long)T_*C_, 0, 0, (long)D_*C_, (long)H_*T_*D_, (long)T_*D_, H_,
            nullptr, 1.f, F_OUTH);
    }
    // 3b. vt[b,h,D,T] = WvT[D,C] @ h[T,C]^T (fp16 out)
    {
        dim3 grid(T_/128, D_/128, B_*H_);
        mma_h<<<grid, 256, SMEM_H>>>(WvT, hh, vth, C_, C_, C_, T_,
            0, (long)D_*C_, (long)T_*C_, 0, (long)H_*D_*T_, (long)D_*T_, H_,
            nullptr, 1.f, F_OUTH);
    }

    // 4. scores = q @ k^T * D^-0.5 (fp32 out, causal tile skip)
    {
        dim3 grid(T_/128, T_/128, B_*H_);
        mma_h<<<grid, 256, SMEM_H>>>(qh, kh, wei, D_, D_, D_, T_,
            (long)H_*T_*D_, (long)T_*D_, (long)H_*T_*D_, (long)T_*D_,
            (long)H_*T_*T_, (long)T_*T_, H_,
            nullptr, rsqrtf((float)D_), F_CSKIP);
    }

    // 5. softmax: fp32 scores -> fp16 probs (pad to 128)
    softmax_kernel<<<B_*H_*T_, 256>>>(wei, ph);

    // 6. att = probs @ vt^T -> [B,T,HD] fp16, causal K-limit
    {
        dim3 grid(D_/128, T_/128, B_*H_);
        mma_h<<<grid, 256, SMEM_H>>>(ph, vth, ath, T_, T_, T_, HD_,
            (long)H_*T_*T_, (long)T_*T_, (long)H_*D_*T_, (long)D_*T_,
            (long)T_*HD_, (long)D_, H_,
            nullptr, 1.f, F_CAUSALK | F_OUTH);
    }

    // 7. x += att @ WoT^T + bo (fp32)
    mma_h<<<dim3(C_/128, (B_*T_)/128, 1), 256, SMEM_H>>>(
        ath, WoT, x, HD_, HD_, HD_, C_,
        0, 0, 0, 0, 0, 0, 1, bo, 1.f, F_BIAS | F_ADDC);

    // 8. LN2 -> fp16
    ln_kernel<<<B_*T_, 256>>>(x, hh, g2, be2);

    // 9. ffn = relu(h @ W1T^T + b1) (fp16 out)
    mma_h<<<dim3(FF_/128, (B_*T_)/128, 1), 256, SMEM_H>>>(
        hh, W1T, fh, C_, C_, C_, FF_,
        0, 0, 0, 0, 0, 0, 1, b1, 1.f, F_BIAS | F_RELU | F_OUTH);

    // 10. x += ffn @ W2T^T + b2 (fp32)
    mma_h<<<dim3(C_/128, (B_*T_)/128, 1), 256, SMEM_H>>>(
        fh, W2T, x, FF_, FF_, FF_, C_,
        0, 0, 0, 0, 0, 0, 1, b2, 1.f, F_BIAS | F_ADDC);

    // 11. final LN -> fp16
    ln_kernel<<<B_*T_, 256>>>(x, hh, gf, bef);

    // 12. logits = h @ WlmT^T + blm (fp32 out, M-tiles on fast axis for L2 reuse)
    mma_h<<<dim3((B_*T_)/128, V_/128, 1), 256, SMEM_H>>>(
        hh, WlmT, out, C_, C_, C_, V_,
        0, 0, 0, 0, 0, 0, 1, blm, 1.f, F_BIAS | F_SWAPXY);
}